// round 14
// baseline (speedup 1.0000x reference)
#include <cuda_runtime.h>
#include <cuda_bf16.h>
#include <cuda_fp16.h>
#include <cstdint>
#include <math.h>

// Problem constants
constexpr int B_  = 8;
constexpr int CH  = 512;
constexpr int T   = 1024;
constexpr int H   = 8;
constexpr int KC  = 64;    // head dim
constexpr int BAND = 256;  // block_length
constexpr int NEL = B_ * CH * T;        // 4M elements

// ---------------------------------------------------------------------------
// Scratch (__device__ globals; allocation-free rule)
// ---------------------------------------------------------------------------
__device__ __half g_x16[NEL];                    // x single fp16 (B of QKV gemms)
__device__ __half g_c16[NEL];                    // c single fp16
__device__ __half g_q16h[NEL], g_q16l[NEL];      // Q fp16 hi/lo (A of S)
__device__ __half g_k16[NEL];                    // K single fp16
__device__ __half g_v16[NEL];                    // V single fp16
__device__ __half g_a16[NEL];                    // attn out single fp16 (B of O gemm)
__device__ __half g_wqh[CH*CH], g_wql[CH*CH];    // W splits fp16 hi/lo
__device__ __half g_wkh[CH*CH], g_wkl[CH*CH];
__device__ __half g_wvh[CH*CH], g_wvl[CH*CH];
__device__ __half g_woh[CH*CH], g_wol[CH*CH];

// ---------------------------------------------------------------------------
// helpers
// ---------------------------------------------------------------------------
__device__ __forceinline__ uint32_t smem_u32(const void* p) {
    uint32_t a;
    asm("{ .reg .u64 t; cvta.to.shared.u64 t, %1; cvt.u32.u64 %0, t; }"
        : "=r"(a) : "l"(p));
    return a;
}
#define LDSM4(r, addr) \
    asm volatile("ldmatrix.sync.aligned.m8n8.x4.shared.b16 {%0,%1,%2,%3}, [%4];" \
        : "=r"((r)[0]), "=r"((r)[1]), "=r"((r)[2]), "=r"((r)[3]) : "r"(addr))
#define LDSM4T(r, addr) \
    asm volatile("ldmatrix.sync.aligned.m8n8.x4.trans.shared.b16 {%0,%1,%2,%3}, [%4];" \
        : "=r"((r)[0]), "=r"((r)[1]), "=r"((r)[2]), "=r"((r)[3]) : "r"(addr))
#define MMA_FP(d, a, b) \
    asm volatile("mma.sync.aligned.m16n8k16.row.col.f32.f16.f16.f32 " \
        "{%0,%1,%2,%3}, {%4,%5,%6,%7}, {%8,%9}, {%0,%1,%2,%3};" \
        : "+f"((d)[0]), "+f"((d)[1]), "+f"((d)[2]), "+f"((d)[3]) \
        : "r"((a)[0]), "r"((a)[1]), "r"((a)[2]), "r"((a)[3]), \
          "r"((b)[0]), "r"((b)[1]))
#define CP_ASYNC16(saddr, gptr) \
    asm volatile("cp.async.cg.shared.global [%0], [%1], 16;" :: "r"(saddr), "l"(gptr))
#define CP_COMMIT() asm volatile("cp.async.commit_group;" ::: "memory")
#define CP_WAIT1()  asm volatile("cp.async.wait_group 1;" ::: "memory")
#define CP_WAIT0()  asm volatile("cp.async.wait_group 0;" ::: "memory")

__device__ __forceinline__ uint32_t pack_hi_h(float x, float y) {
    __half a = __float2half_rn(x), b = __float2half_rn(y);
    return (uint32_t)__half_as_ushort(a) | ((uint32_t)__half_as_ushort(b) << 16);
}
__device__ __forceinline__ uint32_t pack_lo_h(float x, float y) {
    __half a = __float2half_rn(x), b = __float2half_rn(y);
    __half ra = __float2half_rn(x - __half2float(a));
    __half rb = __float2half_rn(y - __half2float(b));
    return (uint32_t)__half_as_ushort(ra) | ((uint32_t)__half_as_ushort(rb) << 16);
}

// ---------------------------------------------------------------------------
// Fused convert, one launch:
//  x, c -> single fp16;  Wq..Wo -> fp16 hi/lo splits.
// ---------------------------------------------------------------------------
constexpr int NB_BIG = NEL / 4 / 256;       // 4096
constexpr int NB_W   = CH * CH / 4 / 256;   // 256
constexpr int NB_ALL = 2 * NB_BIG + 4 * NB_W;

__global__ void convert_all_kernel(
    const float* __restrict__ x,  __half* __restrict__ x16,
    const float* __restrict__ c,  __half* __restrict__ c16,
    const float* __restrict__ Wq, __half* __restrict__ wqh, __half* __restrict__ wql,
    const float* __restrict__ Wk, __half* __restrict__ wkh, __half* __restrict__ wkl,
    const float* __restrict__ Wv, __half* __restrict__ wvh, __half* __restrict__ wvl,
    const float* __restrict__ Wo, __half* __restrict__ woh, __half* __restrict__ wol)
{
    int bid = blockIdx.x;
    if (bid < 2 * NB_BIG) {
        const float* src = (bid < NB_BIG) ? x : c;
        __half* dst      = (bid < NB_BIG) ? x16 : c16;
        int i = ((bid < NB_BIG) ? bid : bid - NB_BIG) * 256 + threadIdx.x;
        float4 v = ((const float4*)src)[i];
        ((uint2*)dst)[i] = make_uint2(pack_hi_h(v.x, v.y), pack_hi_h(v.z, v.w));
    } else {
        int wb = bid - 2 * NB_BIG;
        int w  = wb / NB_W;
        const float* src; __half *h, *l;
        if (w == 0)      { src = Wq; h = wqh; l = wql; }
        else if (w == 1) { src = Wk; h = wkh; l = wkl; }
        else if (w == 2) { src = Wv; h = wvh; l = wvl; }
        else             { src = Wo; h = woh; l = wol; }
        int i = (wb - w * NB_W) * 256 + threadIdx.x;
        float4 v = ((const float4*)src)[i];
        ((uint2*)h)[i] = make_uint2(pack_hi_h(v.x, v.y), pack_hi_h(v.z, v.w));
        ((uint2*)l)[i] = make_uint2(pack_lo_h(v.x, v.y), pack_lo_h(v.z, v.w));
    }
}

// ===========================================================================
// GEMM core, fp16 2-term: acc = Wh@B + Wl@B (W exact, B single fp16).
// CTA 128x128, K-chunk 32, 8 warps (32x64 warp tile), cp.async double-buffer.
// ===========================================================================
constexpr int GK = 512, GN = 1024;
constexpr int BM = 128, BN = 128, BKC = 32;
constexpr int NCHUNK = GK / BKC;            // 16
constexpr int LDA_S = 40;                   // fp16 elems/row (32 + 8 pad)
constexpr int LDB_S = 136;                  // 128 + 8 pad
constexpr int A_BYTES = BM * LDA_S * 2;     // 10240
constexpr int B_BYTES = BKC * LDB_S * 2;    // 8704
constexpr int OFF_AHI = 0;
constexpr int OFF_ALO = A_BYTES;
constexpr int OFF_B   = 2 * A_BYTES;
constexpr int STAGE   = 2 * A_BYTES + B_BYTES;   // 29184
constexpr int GEMM_SMEM = 2 * STAGE;             // 58368

struct GemmAcc { float a[2][8][4]; };

__device__ __forceinline__ void gemm_mainloop16(
    uint32_t sbase,
    const __half* __restrict__ Ah, const __half* __restrict__ Al,
    const __half* __restrict__ Bb,
    int bm0, int bn0, int tid, int lane, int warp_m, int warp_n, GemmAcc& A)
{
    #pragma unroll
    for (int mt = 0; mt < 2; mt++)
        #pragma unroll
        for (int j = 0; j < 8; j++)
            #pragma unroll
            for (int e = 0; e < 4; e++) A.a[mt][j][e] = 0.f;

    auto issue = [&](int c) {
        const int k0 = c * BKC;
        const uint32_t st = sbase + (c & 1) * STAGE;
        #pragma unroll
        for (int i = 0; i < 2; i++) {
            int idx = tid + i * 256;
            int m = idx >> 2, k8 = idx & 3;
            uint32_t ao = st + (uint32_t)(m * LDA_S + k8 * 8) * 2;
            const __half* ga = &Ah[(size_t)(bm0 + m) * GK + k0 + k8 * 8];
            CP_ASYNC16(ao + OFF_AHI, ga);
            CP_ASYNC16(ao + OFF_ALO, &Al[(size_t)(bm0 + m) * GK + k0 + k8 * 8]);
            int kk = idx >> 4, n8 = idx & 15;
            CP_ASYNC16(st + OFF_B + (uint32_t)(kk * LDB_S + n8 * 8) * 2,
                       &Bb[(size_t)(k0 + kk) * GN + bn0 + n8 * 8]);
        }
        CP_COMMIT();
    };

    auto compute = [&](int s) {
        const uint32_t aHi = sbase + s * STAGE + OFF_AHI;
        const uint32_t aLo = sbase + s * STAGE + OFF_ALO;
        const uint32_t bS  = sbase + s * STAGE + OFF_B;
        #pragma unroll
        for (int ks = 0; ks < 2; ks++) {
            const int k0 = ks * 16;
            uint32_t ah[2][4], al[2][4];
            #pragma unroll
            for (int mt = 0; mt < 2; mt++) {
                int m0 = warp_m * 32 + mt * 16;
                uint32_t off = (uint32_t)((m0 + (lane & 15)) * LDA_S
                                          + k0 + (lane >> 4) * 8) * 2;
                LDSM4(ah[mt], aHi + off);
                LDSM4(al[mt], aLo + off);
            }
            uint32_t bh[8][2];
            #pragma unroll
            for (int j2 = 0; j2 < 4; j2++) {
                int n0 = warp_n * 64 + j2 * 16;
                uint32_t off = (uint32_t)((k0 + (lane & 15)) * LDB_S
                                          + n0 + (lane >> 4) * 8) * 2;
                uint32_t r[4];
                LDSM4T(r, bS + off);
                bh[2*j2][0] = r[0]; bh[2*j2][1] = r[1];
                bh[2*j2+1][0] = r[2]; bh[2*j2+1][1] = r[3];
            }
            #pragma unroll
            for (int mt = 0; mt < 2; mt++)
                #pragma unroll
                for (int j = 0; j < 8; j++) {
                    MMA_FP(A.a[mt][j], ah[mt], bh[j]);
                    MMA_FP(A.a[mt][j], al[mt], bh[j]);
                }
        }
    };

    issue(0);
    for (int c = 0; c < NCHUNK; ++c) {
        if (c + 1 < NCHUNK) { issue(c + 1); CP_WAIT1(); }
        else                { CP_WAIT0(); }
        __syncthreads();
        compute(c & 1);
        __syncthreads();
    }
}

// Fused Q/K/V projection GEMM. z = proj*8 + batch.
__global__ __launch_bounds__(256, 2)
void gemm_qkv_kernel(
    const __half* __restrict__ wqh, const __half* __restrict__ wql, const float* __restrict__ bq,
    const __half* __restrict__ wkh, const __half* __restrict__ wkl, const float* __restrict__ bk,
    const __half* __restrict__ wvh, const __half* __restrict__ wvl, const float* __restrict__ bv,
    const __half* __restrict__ x16, const __half* __restrict__ c16,
    __half* __restrict__ qh, __half* __restrict__ ql,
    __half* __restrict__ ks, __half* __restrict__ vs)
{
    extern __shared__ __align__(128) char smem[];
    const int tid = threadIdx.x, lane = tid & 31, wid = tid >> 5;
    const int warp_m = wid & 3, warp_n = wid >> 2;
    const int proj = blockIdx.z >> 3, b = blockIdx.z & 7;
    const int bm0 = blockIdx.y * BM, bn0 = blockIdx.x * BN;

    const __half *Ah, *Al, *Bg; const float* bias;
    if (proj == 0)      { Ah = wqh; Al = wql; bias = bq; Bg = x16; }
    else if (proj == 1) { Ah = wkh; Al = wkl; bias = bk; Bg = c16; }
    else                { Ah = wvh; Al = wvl; bias = bv; Bg = c16; }
    const __half* Bb = Bg + (size_t)b * GK * GN;

    GemmAcc A;
    gemm_mainloop16(smem_u32(smem), Ah, Al, Bb, bm0, bn0,
                    tid, lane, warp_m, warp_n, A);

    const float scale = (proj == 0) ? 0.125f : 1.0f;
    __half* outs = (proj == 1) ? ks : vs;
    #pragma unroll
    for (int mt = 0; mt < 2; mt++) {
        int m0 = bm0 + warp_m * 32 + mt * 16 + (lane >> 2);
        float bv0 = bias[m0], bv1 = bias[m0 + 8];
        #pragma unroll
        for (int j = 0; j < 8; j++) {
            int n0 = bn0 + warp_n * 64 + j * 8 + 2 * (lane & 3);
            float r00 = (A.a[mt][j][0] + bv0) * scale;
            float r01 = (A.a[mt][j][1] + bv0) * scale;
            float r10 = (A.a[mt][j][2] + bv1) * scale;
            float r11 = (A.a[mt][j][3] + bv1) * scale;
            size_t o0 = (size_t)b * CH * GN + (size_t)m0 * GN + n0;
            size_t o1 = (size_t)b * CH * GN + (size_t)(m0 + 8) * GN + n0;
            if (proj == 0) {
                *(uint32_t*)&qh[o0] = pack_hi_h(r00, r01);
                *(uint32_t*)&ql[o0] = pack_lo_h(r00, r01);
                *(uint32_t*)&qh[o1] = pack_hi_h(r10, r11);
                *(uint32_t*)&ql[o1] = pack_lo_h(r10, r11);
            } else {
                *(uint32_t*)&outs[o0] = pack_hi_h(r00, r01);
                *(uint32_t*)&outs[o1] = pack_hi_h(r10, r11);
            }
        }
    }
}

// O-projection GEMM: fp32 out + bias.
__global__ __launch_bounds__(256, 2)
void gemm_o_kernel(const __half* __restrict__ Ah, const __half* __restrict__ Al,
                   const float* __restrict__ bias,
                   const __half* __restrict__ Bg, float* __restrict__ outf)
{
    extern __shared__ __align__(128) char smem[];
    const int tid = threadIdx.x, lane = tid & 31, wid = tid >> 5;
    const int warp_m = wid & 3, warp_n = wid >> 2;
    const int b = blockIdx.z;
    const int bm0 = blockIdx.y * BM, bn0 = blockIdx.x * BN;
    const __half* Bb = Bg + (size_t)b * GK * GN;

    GemmAcc A;
    gemm_mainloop16(smem_u32(smem), Ah, Al, Bb, bm0, bn0,
                    tid, lane, warp_m, warp_n, A);

    #pragma unroll
    for (int mt = 0; mt < 2; mt++) {
        int m0 = bm0 + warp_m * 32 + mt * 16 + (lane >> 2);
        float bv0 = bias[m0], bv1 = bias[m0 + 8];
        #pragma unroll
        for (int j = 0; j < 8; j++) {
            int n0 = bn0 + warp_n * 64 + j * 8 + 2 * (lane & 3);
            size_t o0 = (size_t)b * CH * GN + (size_t)m0 * GN + n0;
            size_t o1 = (size_t)b * CH * GN + (size_t)(m0 + 8) * GN + n0;
            *(float2*)&outf[o0] = make_float2(A.a[mt][j][0] + bv0, A.a[mt][j][1] + bv0);
            *(float2*)&outf[o1] = make_float2(A.a[mt][j][2] + bv1, A.a[mt][j][3] + bv1);
        }
    }
}

// ===========================================================================
// Banded flash attention, fp16 2-term (unchanged math; fp16-single output).
// ===========================================================================
constexpr int ALD = 72;
constexpr int TILE_B = 64 * ALD * 2;
constexpr int AQH = 0, AQL = TILE_B, AKH = 2*TILE_B, AVH = 3*TILE_B, ATAB = 4*TILE_B;
constexpr int ATTN_SMEM = 4 * TILE_B + 512 * 4;   // 38912

__global__ __launch_bounds__(128)
void attn_mma_kernel(const __half* __restrict__ Qh, const __half* __restrict__ Ql,
                     const __half* __restrict__ Kh, const __half* __restrict__ Vh,
                     __half* __restrict__ Oa)
{
    extern __shared__ __align__(128) char sm[];
    float* tab = (float*)(sm + ATAB);
    const uint32_t sb = smem_u32(sm);

    const int bh  = blockIdx.y;
    const int i0  = blockIdx.x * 64;
    const int tid = threadIdx.x;
    const int lane = tid & 31;
    const int warp = tid >> 5;
    const int m0w  = warp * 16;
    const size_t hb = (size_t)bh * KC * T;

    for (int idx = tid; idx < 512; idx += 128)
        tab[idx] = (idx <= BAND) ? -log1pf((float)idx) : -1e30f;

    #pragma unroll
    for (int it = 0; it < 4; it++) {
        int idx = tid + it * 128;
        int d = idx >> 3, c8 = idx & 7;
        *(uint4*)(sm + AQH + (d * ALD + c8 * 8) * 2) =
            *(const uint4*)&Qh[hb + (size_t)d * T + i0 + c8 * 8];
        *(uint4*)(sm + AQL + (d * ALD + c8 * 8) * 2) =
            *(const uint4*)&Ql[hb + (size_t)d * T + i0 + c8 * 8];
    }
    __syncthreads();

    uint32_t qfh[4][4], qfl[4][4];
    #pragma unroll
    for (int kt = 0; kt < 4; kt++) {
        uint32_t roff = (uint32_t)((kt * 16 + (lane & 7) + (lane >> 4) * 8) * ALD
                                   + m0w + ((lane >> 3) & 1) * 8) * 2;
        LDSM4T(qfh[kt], sb + AQH + roff);
        LDSM4T(qfl[kt], sb + AQL + roff);
    }

    float o[8][4];
    #pragma unroll
    for (int nt = 0; nt < 8; nt++)
        #pragma unroll
        for (int e = 0; e < 4; e++) o[nt][e] = 0.f;
    float m_[2] = {-1e30f, -1e30f}, l_[2] = {0.f, 0.f};

    int j_lo = i0 - BAND; if (j_lo < 0) j_lo = 0;
    int j_hi = i0 + BAND; if (j_hi > T - 64) j_hi = T - 64;

    const int i_r = i0 + m0w + (lane >> 2);

    for (int j0 = j_lo; j0 <= j_hi; j0 += 64) {
        __syncthreads();
        #pragma unroll
        for (int it = 0; it < 4; it++) {
            int idx = tid + it * 128;
            int d = idx >> 3, c8 = idx & 7;
            size_t g = hb + (size_t)d * T + j0 + c8 * 8;
            uint32_t so = (uint32_t)(d * ALD + c8 * 8) * 2;
            *(uint4*)(sm + AKH + so) = *(const uint4*)&Kh[g];
            *(uint4*)(sm + AVH + so) = *(const uint4*)&Vh[g];
        }
        __syncthreads();

        float s[8][4];
        #pragma unroll
        for (int nt = 0; nt < 8; nt++)
            #pragma unroll
            for (int e = 0; e < 4; e++) s[nt][e] = 0.f;

        #pragma unroll
        for (int kt = 0; kt < 4; kt++) {
            #pragma unroll
            for (int p = 0; p < 4; p++) {
                uint32_t off = (uint32_t)((kt * 16 + (lane & 15)) * ALD
                                          + p * 16 + (lane >> 4) * 8) * 2;
                uint32_t rh[4];
                LDSM4T(rh, sb + AKH + off);
                MMA_FP(s[2*p],   qfh[kt], rh);
                MMA_FP(s[2*p],   qfl[kt], rh);
                MMA_FP(s[2*p+1], qfh[kt], rh + 2);
                MMA_FP(s[2*p+1], qfl[kt], rh + 2);
            }
        }

        #pragma unroll
        for (int nt = 0; nt < 8; nt++) {
            int jc = j0 + nt * 8 + 2 * (lane & 3);
            s[nt][0] += tab[abs(i_r - jc)];
            s[nt][1] += tab[abs(i_r - jc - 1)];
            s[nt][2] += tab[abs(i_r + 8 - jc)];
            s[nt][3] += tab[abs(i_r + 8 - jc - 1)];
        }

        float rm0 = -1e30f, rm1 = -1e30f;
        #pragma unroll
        for (int nt = 0; nt < 8; nt++) {
            rm0 = fmaxf(rm0, fmaxf(s[nt][0], s[nt][1]));
            rm1 = fmaxf(rm1, fmaxf(s[nt][2], s[nt][3]));
        }
        rm0 = fmaxf(rm0, __shfl_xor_sync(0xffffffffu, rm0, 1));
        rm0 = fmaxf(rm0, __shfl_xor_sync(0xffffffffu, rm0, 2));
        rm1 = fmaxf(rm1, __shfl_xor_sync(0xffffffffu, rm1, 1));
        rm1 = fmaxf(rm1, __shfl_xor_sync(0xffffffffu, rm1, 2));
        float mn0 = fmaxf(m_[0], rm0), mn1 = fmaxf(m_[1], rm1);
        float al0 = __expf(m_[0] - mn0), al1 = __expf(m_[1] - mn1);
        m_[0] = mn0; m_[1] = mn1;
        float sum0 = 0.f, sum1 = 0.f;
        #pragma unroll
        for (int nt = 0; nt < 8; nt++) {
            s[nt][0] = __expf(s[nt][0] - mn0); sum0 += s[nt][0];
            s[nt][1] = __expf(s[nt][1] - mn0); sum0 += s[nt][1];
            s[nt][2] = __expf(s[nt][2] - mn1); sum1 += s[nt][2];
            s[nt][3] = __expf(s[nt][3] - mn1); sum1 += s[nt][3];
        }
        sum0 += __shfl_xor_sync(0xffffffffu, sum0, 1);
        sum0 += __shfl_xor_sync(0xffffffffu, sum0, 2);
        sum1 += __shfl_xor_sync(0xffffffffu, sum1, 1);
        sum1 += __shfl_xor_sync(0xffffffffu, sum1, 2);
        l_[0] = l_[0] * al0 + sum0;
        l_[1] = l_[1] * al1 + sum1;
        #pragma unroll
        for (int nt = 0; nt < 8; nt++) {
            o[nt][0] *= al0; o[nt][1] *= al0;
            o[nt][2] *= al1; o[nt][3] *= al1;
        }

        uint32_t pfh[4][4], pfl[4][4];
        #pragma unroll
        for (int jt = 0; jt < 4; jt++) {
            pfh[jt][0] = pack_hi_h(s[2*jt][0],   s[2*jt][1]);
            pfl[jt][0] = pack_lo_h(s[2*jt][0],   s[2*jt][1]);
            pfh[jt][1] = pack_hi_h(s[2*jt][2],   s[2*jt][3]);
            pfl[jt][1] = pack_lo_h(s[2*jt][2],   s[2*jt][3]);
            pfh[jt][2] = pack_hi_h(s[2*jt+1][0], s[2*jt+1][1]);
            pfl[jt][2] = pack_lo_h(s[2*jt+1][0], s[2*jt+1][1]);
            pfh[jt][3] = pack_hi_h(s[2*jt+1][2], s[2*jt+1][3]);
            pfl[jt][3] = pack_lo_h(s[2*jt+1][2], s[2*jt+1][3]);
        }

        #pragma unroll
        for (int kt = 0; kt < 4; kt++) {
            #pragma unroll
            for (int p = 0; p < 4; p++) {
                uint32_t off = (uint32_t)((p * 16 + (lane & 7) + (lane >> 4) * 8) * ALD
                                          + kt * 16 + ((lane >> 3) & 1) * 8) * 2;
                uint32_t rh[4];
                LDSM4(rh, sb + AVH + off);
                MMA_FP(o[2*p],   pfh[kt], rh);
                MMA_FP(o[2*p],   pfl[kt], rh);
                MMA_FP(o[2*p+1], pfh[kt], rh + 2);
                MMA_FP(o[2*p+1], pfl[kt], rh + 2);
            }
        }
    }

    float inv0 = 1.f / l_[0], inv1 = 1.f / l_[1];
    #pragma unroll
    for (int nt = 0; nt < 8; nt++) {
        int d = nt * 8 + 2 * (lane & 3);
        size_t g00 = hb + (size_t)d * T + i_r;
        size_t g01 = hb + (size_t)(d + 1) * T + i_r;
        Oa[g00]     = __float2half_rn(o[nt][0] * inv0);
        Oa[g01]     = __float2half_rn(o[nt][1] * inv0);
        Oa[g00 + 8] = __float2half_rn(o[nt][2] * inv1);
        Oa[g01 + 8] = __float2half_rn(o[nt][3] * inv1);
    }
}

// ===========================================================================
// Launch
// ===========================================================================
extern "C" void kernel_launch(void* const* d_in, const int* in_sizes, int n_in,
                              void* d_out, int out_size)
{
    const float* x  = (const float*)d_in[0];
    const float* c  = (const float*)d_in[1];
    const float* Wq = (const float*)d_in[3];
    const float* bq = (const float*)d_in[4];
    const float* Wk = (const float*)d_in[5];
    const float* bk = (const float*)d_in[6];
    const float* Wv = (const float*)d_in[7];
    const float* bv = (const float*)d_in[8];
    const float* Wo = (const float*)d_in[9];
    const float* bo = (const float*)d_in[10];
    float* out = (float*)d_out;

    __half *x16, *c16, *qh, *ql, *ks, *vs, *a16;
    __half *wqh, *wql, *wkh, *wkl, *wvh, *wvl, *woh, *wol;
    cudaGetSymbolAddress((void**)&x16, g_x16);
    cudaGetSymbolAddress((void**)&c16, g_c16);
    cudaGetSymbolAddress((void**)&qh, g_q16h); cudaGetSymbolAddress((void**)&ql, g_q16l);
    cudaGetSymbolAddress((void**)&ks, g_k16);  cudaGetSymbolAddress((void**)&vs, g_v16);
    cudaGetSymbolAddress((void**)&a16, g_a16);
    cudaGetSymbolAddress((void**)&wqh, g_wqh); cudaGetSymbolAddress((void**)&wql, g_wql);
    cudaGetSymbolAddress((void**)&wkh, g_wkh); cudaGetSymbolAddress((void**)&wkl, g_wkl);
    cudaGetSymbolAddress((void**)&wvh, g_wvh); cudaGetSymbolAddress((void**)&wvl, g_wvl);
    cudaGetSymbolAddress((void**)&woh, g_woh); cudaGetSymbolAddress((void**)&wol, g_wol);

    cudaFuncSetAttribute(gemm_qkv_kernel,
                         cudaFuncAttributeMaxDynamicSharedMemorySize, GEMM_SMEM);
    cudaFuncSetAttribute(gemm_o_kernel,
                         cudaFuncAttributeMaxDynamicSharedMemorySize, GEMM_SMEM);
    cudaFuncSetAttribute(attn_mma_kernel,
                         cudaFuncAttributeMaxDynamicSharedMemorySize, ATTN_SMEM);

    convert_all_kernel<<<NB_ALL, 256>>>(x, x16, c, c16,
                                        Wq, wqh, wql, Wk, wkh, wkl,
                                        Wv, wvh, wvl, Wo, woh, wol);

    gemm_qkv_kernel<<<dim3(GN / BN, CH / BM, 3 * B_), 256, GEMM_SMEM>>>(
        wqh, wql, bq, wkh, wkl, bk, wvh, wvl, bv,
        x16, c16, qh, ql, ks, vs);

    attn_mma_kernel<<<dim3(T / 64, B_ * H), 128, ATTN_SMEM>>>(
        qh, ql, ks, vs, a16);

    gemm_o_kernel<<<dim3(GN / BN, CH / BM, B_), 256, GEMM_SMEM>>>(
        woh, wol, bo, a16, out);
}

// round 15
// speedup vs baseline: 1.0050x; 1.0050x over previous
#include <cuda_runtime.h>
#include <cuda_bf16.h>
#include <cuda_fp16.h>
#include <cstdint>
#include <math.h>

// Problem constants
constexpr int B_  = 8;
constexpr int CH  = 512;
constexpr int T   = 1024;
constexpr int H   = 8;
constexpr int KC  = 64;    // head dim
constexpr int BAND = 256;  // block_length
constexpr int NEL = B_ * CH * T;        // 4M elements

// ---------------------------------------------------------------------------
// Scratch (__device__ globals; allocation-free rule)
// ---------------------------------------------------------------------------
__device__ __half g_x16[NEL];                    // x single fp16 (B of QKV gemms)
__device__ __half g_c16[NEL];                    // c single fp16
__device__ __half g_q16h[NEL], g_q16l[NEL];      // Q fp16 hi/lo (A of S)
__device__ __half g_k16[NEL];                    // K single fp16
__device__ __half g_v16[NEL];                    // V single fp16
__device__ __half g_a16[NEL];                    // attn out single fp16 (B of O gemm)
__device__ __half g_wqh[CH*CH], g_wql[CH*CH];    // W splits fp16 hi/lo
__device__ __half g_wkh[CH*CH], g_wkl[CH*CH];
__device__ __half g_wvh[CH*CH], g_wvl[CH*CH];
__device__ __half g_woh[CH*CH], g_wol[CH*CH];

// ---------------------------------------------------------------------------
// helpers
// ---------------------------------------------------------------------------
__device__ __forceinline__ uint32_t smem_u32(const void* p) {
    uint32_t a;
    asm("{ .reg .u64 t; cvta.to.shared.u64 t, %1; cvt.u32.u64 %0, t; }"
        : "=r"(a) : "l"(p));
    return a;
}
#define LDSM4(r, addr) \
    asm volatile("ldmatrix.sync.aligned.m8n8.x4.shared.b16 {%0,%1,%2,%3}, [%4];" \
        : "=r"((r)[0]), "=r"((r)[1]), "=r"((r)[2]), "=r"((r)[3]) : "r"(addr))
#define LDSM4T(r, addr) \
    asm volatile("ldmatrix.sync.aligned.m8n8.x4.trans.shared.b16 {%0,%1,%2,%3}, [%4];" \
        : "=r"((r)[0]), "=r"((r)[1]), "=r"((r)[2]), "=r"((r)[3]) : "r"(addr))
#define MMA_FP(d, a, b) \
    asm volatile("mma.sync.aligned.m16n8k16.row.col.f32.f16.f16.f32 " \
        "{%0,%1,%2,%3}, {%4,%5,%6,%7}, {%8,%9}, {%0,%1,%2,%3};" \
        : "+f"((d)[0]), "+f"((d)[1]), "+f"((d)[2]), "+f"((d)[3]) \
        : "r"((a)[0]), "r"((a)[1]), "r"((a)[2]), "r"((a)[3]), \
          "r"((b)[0]), "r"((b)[1]))
#define CP_ASYNC16(saddr, gptr) \
    asm volatile("cp.async.cg.shared.global [%0], [%1], 16;" :: "r"(saddr), "l"(gptr))
#define CP_COMMIT() asm volatile("cp.async.commit_group;" ::: "memory")
#define CP_WAIT1()  asm volatile("cp.async.wait_group 1;" ::: "memory")
#define CP_WAIT0()  asm volatile("cp.async.wait_group 0;" ::: "memory")

__device__ __forceinline__ uint32_t pack_hi_h(float x, float y) {
    __half a = __float2half_rn(x), b = __float2half_rn(y);
    return (uint32_t)__half_as_ushort(a) | ((uint32_t)__half_as_ushort(b) << 16);
}
__device__ __forceinline__ uint32_t pack_lo_h(float x, float y) {
    __half a = __float2half_rn(x), b = __float2half_rn(y);
    __half ra = __float2half_rn(x - __half2float(a));
    __half rb = __float2half_rn(y - __half2float(b));
    return (uint32_t)__half_as_ushort(ra) | ((uint32_t)__half_as_ushort(rb) << 16);
}

// ---------------------------------------------------------------------------
// Fused convert, one launch:
//  x, c -> single fp16;  Wq..Wo -> fp16 hi/lo splits.
// ---------------------------------------------------------------------------
constexpr int NB_BIG = NEL / 4 / 256;       // 4096
constexpr int NB_W   = CH * CH / 4 / 256;   // 256
constexpr int NB_ALL = 2 * NB_BIG + 4 * NB_W;

__global__ void convert_all_kernel(
    const float* __restrict__ x,  __half* __restrict__ x16,
    const float* __restrict__ c,  __half* __restrict__ c16,
    const float* __restrict__ Wq, __half* __restrict__ wqh, __half* __restrict__ wql,
    const float* __restrict__ Wk, __half* __restrict__ wkh, __half* __restrict__ wkl,
    const float* __restrict__ Wv, __half* __restrict__ wvh, __half* __restrict__ wvl,
    const float* __restrict__ Wo, __half* __restrict__ woh, __half* __restrict__ wol)
{
    int bid = blockIdx.x;
    if (bid < 2 * NB_BIG) {
        const float* src = (bid < NB_BIG) ? x : c;
        __half* dst      = (bid < NB_BIG) ? x16 : c16;
        int i = ((bid < NB_BIG) ? bid : bid - NB_BIG) * 256 + threadIdx.x;
        float4 v = ((const float4*)src)[i];
        ((uint2*)dst)[i] = make_uint2(pack_hi_h(v.x, v.y), pack_hi_h(v.z, v.w));
    } else {
        int wb = bid - 2 * NB_BIG;
        int w  = wb / NB_W;
        const float* src; __half *h, *l;
        if (w == 0)      { src = Wq; h = wqh; l = wql; }
        else if (w == 1) { src = Wk; h = wkh; l = wkl; }
        else if (w == 2) { src = Wv; h = wvh; l = wvl; }
        else             { src = Wo; h = woh; l = wol; }
        int i = (wb - w * NB_W) * 256 + threadIdx.x;
        float4 v = ((const float4*)src)[i];
        ((uint2*)h)[i] = make_uint2(pack_hi_h(v.x, v.y), pack_hi_h(v.z, v.w));
        ((uint2*)l)[i] = make_uint2(pack_lo_h(v.x, v.y), pack_lo_h(v.z, v.w));
    }
}

// ===========================================================================
// GEMM core, fp16 2-term: acc = Wh@B + Wl@B (W exact, B single fp16).
// CTA 128x128, K-chunk 32, 8 warps (32x64 warp tile), cp.async double-buffer.
// ===========================================================================
constexpr int GK = 512, GN = 1024;
constexpr int BM = 128, BN = 128, BKC = 32;
constexpr int NCHUNK = GK / BKC;            // 16
constexpr int LDA_S = 40;                   // fp16 elems/row (32 + 8 pad)
constexpr int LDB_S = 136;                  // 128 + 8 pad
constexpr int A_BYTES = BM * LDA_S * 2;     // 10240
constexpr int B_BYTES = BKC * LDB_S * 2;    // 8704
constexpr int OFF_AHI = 0;
constexpr int OFF_ALO = A_BYTES;
constexpr int OFF_B   = 2 * A_BYTES;
constexpr int STAGE   = 2 * A_BYTES + B_BYTES;   // 29184
constexpr int GEMM_SMEM = 2 * STAGE;             // 58368

struct GemmAcc { float a[2][8][4]; };

__device__ __forceinline__ void gemm_mainloop16(
    uint32_t sbase,
    const __half* __restrict__ Ah, const __half* __restrict__ Al,
    const __half* __restrict__ Bb,
    int bm0, int bn0, int tid, int lane, int warp_m, int warp_n, GemmAcc& A)
{
    #pragma unroll
    for (int mt = 0; mt < 2; mt++)
        #pragma unroll
        for (int j = 0; j < 8; j++)
            #pragma unroll
            for (int e = 0; e < 4; e++) A.a[mt][j][e] = 0.f;

    auto issue = [&](int c) {
        const int k0 = c * BKC;
        const uint32_t st = sbase + (c & 1) * STAGE;
        #pragma unroll
        for (int i = 0; i < 2; i++) {
            int idx = tid + i * 256;
            int m = idx >> 2, k8 = idx & 3;
            uint32_t ao = st + (uint32_t)(m * LDA_S + k8 * 8) * 2;
            const __half* ga = &Ah[(size_t)(bm0 + m) * GK + k0 + k8 * 8];
            CP_ASYNC16(ao + OFF_AHI, ga);
            CP_ASYNC16(ao + OFF_ALO, &Al[(size_t)(bm0 + m) * GK + k0 + k8 * 8]);
            int kk = idx >> 4, n8 = idx & 15;
            CP_ASYNC16(st + OFF_B + (uint32_t)(kk * LDB_S + n8 * 8) * 2,
                       &Bb[(size_t)(k0 + kk) * GN + bn0 + n8 * 8]);
        }
        CP_COMMIT();
    };

    auto compute = [&](int s) {
        const uint32_t aHi = sbase + s * STAGE + OFF_AHI;
        const uint32_t aLo = sbase + s * STAGE + OFF_ALO;
        const uint32_t bS  = sbase + s * STAGE + OFF_B;
        #pragma unroll
        for (int ks = 0; ks < 2; ks++) {
            const int k0 = ks * 16;
            uint32_t ah[2][4], al[2][4];
            #pragma unroll
            for (int mt = 0; mt < 2; mt++) {
                int m0 = warp_m * 32 + mt * 16;
                uint32_t off = (uint32_t)((m0 + (lane & 15)) * LDA_S
                                          + k0 + (lane >> 4) * 8) * 2;
                LDSM4(ah[mt], aHi + off);
                LDSM4(al[mt], aLo + off);
            }
            uint32_t bh[8][2];
            #pragma unroll
            for (int j2 = 0; j2 < 4; j2++) {
                int n0 = warp_n * 64 + j2 * 16;
                uint32_t off = (uint32_t)((k0 + (lane & 15)) * LDB_S
                                          + n0 + (lane >> 4) * 8) * 2;
                uint32_t r[4];
                LDSM4T(r, bS + off);
                bh[2*j2][0] = r[0]; bh[2*j2][1] = r[1];
                bh[2*j2+1][0] = r[2]; bh[2*j2+1][1] = r[3];
            }
            #pragma unroll
            for (int mt = 0; mt < 2; mt++)
                #pragma unroll
                for (int j = 0; j < 8; j++) {
                    MMA_FP(A.a[mt][j], ah[mt], bh[j]);
                    MMA_FP(A.a[mt][j], al[mt], bh[j]);
                }
        }
    };

    issue(0);
    for (int c = 0; c < NCHUNK; ++c) {
        if (c + 1 < NCHUNK) { issue(c + 1); CP_WAIT1(); }
        else                { CP_WAIT0(); }
        __syncthreads();
        compute(c & 1);
        __syncthreads();
    }
}

// Fused Q/K/V projection GEMM. z = proj*8 + batch.
__global__ __launch_bounds__(256, 2)
void gemm_qkv_kernel(
    const __half* __restrict__ wqh, const __half* __restrict__ wql, const float* __restrict__ bq,
    const __half* __restrict__ wkh, const __half* __restrict__ wkl, const float* __restrict__ bk,
    const __half* __restrict__ wvh, const __half* __restrict__ wvl, const float* __restrict__ bv,
    const __half* __restrict__ x16, const __half* __restrict__ c16,
    __half* __restrict__ qh, __half* __restrict__ ql,
    __half* __restrict__ ks, __half* __restrict__ vs)
{
    extern __shared__ __align__(128) char smem[];
    const int tid = threadIdx.x, lane = tid & 31, wid = tid >> 5;
    const int warp_m = wid & 3, warp_n = wid >> 2;
    const int proj = blockIdx.z >> 3, b = blockIdx.z & 7;
    const int bm0 = blockIdx.y * BM, bn0 = blockIdx.x * BN;

    const __half *Ah, *Al, *Bg; const float* bias;
    if (proj == 0)      { Ah = wqh; Al = wql; bias = bq; Bg = x16; }
    else if (proj == 1) { Ah = wkh; Al = wkl; bias = bk; Bg = c16; }
    else                { Ah = wvh; Al = wvl; bias = bv; Bg = c16; }
    const __half* Bb = Bg + (size_t)b * GK * GN;

    GemmAcc A;
    gemm_mainloop16(smem_u32(smem), Ah, Al, Bb, bm0, bn0,
                    tid, lane, warp_m, warp_n, A);

    const float scale = (proj == 0) ? 0.125f : 1.0f;
    __half* outs = (proj == 1) ? ks : vs;
    #pragma unroll
    for (int mt = 0; mt < 2; mt++) {
        int m0 = bm0 + warp_m * 32 + mt * 16 + (lane >> 2);
        float bv0 = bias[m0], bv1 = bias[m0 + 8];
        #pragma unroll
        for (int j = 0; j < 8; j++) {
            int n0 = bn0 + warp_n * 64 + j * 8 + 2 * (lane & 3);
            float r00 = (A.a[mt][j][0] + bv0) * scale;
            float r01 = (A.a[mt][j][1] + bv0) * scale;
            float r10 = (A.a[mt][j][2] + bv1) * scale;
            float r11 = (A.a[mt][j][3] + bv1) * scale;
            size_t o0 = (size_t)b * CH * GN + (size_t)m0 * GN + n0;
            size_t o1 = (size_t)b * CH * GN + (size_t)(m0 + 8) * GN + n0;
            if (proj == 0) {
                *(uint32_t*)&qh[o0] = pack_hi_h(r00, r01);
                *(uint32_t*)&ql[o0] = pack_lo_h(r00, r01);
                *(uint32_t*)&qh[o1] = pack_hi_h(r10, r11);
                *(uint32_t*)&ql[o1] = pack_lo_h(r10, r11);
            } else {
                *(uint32_t*)&outs[o0] = pack_hi_h(r00, r01);
                *(uint32_t*)&outs[o1] = pack_hi_h(r10, r11);
            }
        }
    }
}

// O-projection GEMM: fp32 out + bias.
__global__ __launch_bounds__(256, 2)
void gemm_o_kernel(const __half* __restrict__ Ah, const __half* __restrict__ Al,
                   const float* __restrict__ bias,
                   const __half* __restrict__ Bg, float* __restrict__ outf)
{
    extern __shared__ __align__(128) char smem[];
    const int tid = threadIdx.x, lane = tid & 31, wid = tid >> 5;
    const int warp_m = wid & 3, warp_n = wid >> 2;
    const int b = blockIdx.z;
    const int bm0 = blockIdx.y * BM, bn0 = blockIdx.x * BN;
    const __half* Bb = Bg + (size_t)b * GK * GN;

    GemmAcc A;
    gemm_mainloop16(smem_u32(smem), Ah, Al, Bb, bm0, bn0,
                    tid, lane, warp_m, warp_n, A);

    #pragma unroll
    for (int mt = 0; mt < 2; mt++) {
        int m0 = bm0 + warp_m * 32 + mt * 16 + (lane >> 2);
        float bv0 = bias[m0], bv1 = bias[m0 + 8];
        #pragma unroll
        for (int j = 0; j < 8; j++) {
            int n0 = bn0 + warp_n * 64 + j * 8 + 2 * (lane & 3);
            size_t o0 = (size_t)b * CH * GN + (size_t)m0 * GN + n0;
            size_t o1 = (size_t)b * CH * GN + (size_t)(m0 + 8) * GN + n0;
            *(float2*)&outf[o0] = make_float2(A.a[mt][j][0] + bv0, A.a[mt][j][1] + bv0);
            *(float2*)&outf[o1] = make_float2(A.a[mt][j][2] + bv1, A.a[mt][j][3] + bv1);
        }
    }
}

// ===========================================================================
// Banded flash attention, fp16 2-term (unchanged math; fp16-single output).
// ===========================================================================
constexpr int ALD = 72;
constexpr int TILE_B = 64 * ALD * 2;
constexpr int AQH = 0, AQL = TILE_B, AKH = 2*TILE_B, AVH = 3*TILE_B, ATAB = 4*TILE_B;
constexpr int ATTN_SMEM = 4 * TILE_B + 512 * 4;   // 38912

__global__ __launch_bounds__(128)
void attn_mma_kernel(const __half* __restrict__ Qh, const __half* __restrict__ Ql,
                     const __half* __restrict__ Kh, const __half* __restrict__ Vh,
                     __half* __restrict__ Oa)
{
    extern __shared__ __align__(128) char sm[];
    float* tab = (float*)(sm + ATAB);
    const uint32_t sb = smem_u32(sm);

    const int bh  = blockIdx.y;
    const int i0  = blockIdx.x * 64;
    const int tid = threadIdx.x;
    const int lane = tid & 31;
    const int warp = tid >> 5;
    const int m0w  = warp * 16;
    const size_t hb = (size_t)bh * KC * T;

    for (int idx = tid; idx < 512; idx += 128)
        tab[idx] = (idx <= BAND) ? -log1pf((float)idx) : -1e30f;

    #pragma unroll
    for (int it = 0; it < 4; it++) {
        int idx = tid + it * 128;
        int d = idx >> 3, c8 = idx & 7;
        *(uint4*)(sm + AQH + (d * ALD + c8 * 8) * 2) =
            *(const uint4*)&Qh[hb + (size_t)d * T + i0 + c8 * 8];
        *(uint4*)(sm + AQL + (d * ALD + c8 * 8) * 2) =
            *(const uint4*)&Ql[hb + (size_t)d * T + i0 + c8 * 8];
    }
    __syncthreads();

    uint32_t qfh[4][4], qfl[4][4];
    #pragma unroll
    for (int kt = 0; kt < 4; kt++) {
        uint32_t roff = (uint32_t)((kt * 16 + (lane & 7) + (lane >> 4) * 8) * ALD
                                   + m0w + ((lane >> 3) & 1) * 8) * 2;
        LDSM4T(qfh[kt], sb + AQH + roff);
        LDSM4T(qfl[kt], sb + AQL + roff);
    }

    float o[8][4];
    #pragma unroll
    for (int nt = 0; nt < 8; nt++)
        #pragma unroll
        for (int e = 0; e < 4; e++) o[nt][e] = 0.f;
    float m_[2] = {-1e30f, -1e30f}, l_[2] = {0.f, 0.f};

    int j_lo = i0 - BAND; if (j_lo < 0) j_lo = 0;
    int j_hi = i0 + BAND; if (j_hi > T - 64) j_hi = T - 64;

    const int i_r = i0 + m0w + (lane >> 2);

    for (int j0 = j_lo; j0 <= j_hi; j0 += 64) {
        __syncthreads();
        #pragma unroll
        for (int it = 0; it < 4; it++) {
            int idx = tid + it * 128;
            int d = idx >> 3, c8 = idx & 7;
            size_t g = hb + (size_t)d * T + j0 + c8 * 8;
            uint32_t so = (uint32_t)(d * ALD + c8 * 8) * 2;
            *(uint4*)(sm + AKH + so) = *(const uint4*)&Kh[g];
            *(uint4*)(sm + AVH + so) = *(const uint4*)&Vh[g];
        }
        __syncthreads();

        float s[8][4];
        #pragma unroll
        for (int nt = 0; nt < 8; nt++)
            #pragma unroll
            for (int e = 0; e < 4; e++) s[nt][e] = 0.f;

        #pragma unroll
        for (int kt = 0; kt < 4; kt++) {
            #pragma unroll
            for (int p = 0; p < 4; p++) {
                uint32_t off = (uint32_t)((kt * 16 + (lane & 15)) * ALD
                                          + p * 16 + (lane >> 4) * 8) * 2;
                uint32_t rh[4];
                LDSM4T(rh, sb + AKH + off);
                MMA_FP(s[2*p],   qfh[kt], rh);
                MMA_FP(s[2*p],   qfl[kt], rh);
                MMA_FP(s[2*p+1], qfh[kt], rh + 2);
                MMA_FP(s[2*p+1], qfl[kt], rh + 2);
            }
        }

        #pragma unroll
        for (int nt = 0; nt < 8; nt++) {
            int jc = j0 + nt * 8 + 2 * (lane & 3);
            s[nt][0] += tab[abs(i_r - jc)];
            s[nt][1] += tab[abs(i_r - jc - 1)];
            s[nt][2] += tab[abs(i_r + 8 - jc)];
            s[nt][3] += tab[abs(i_r + 8 - jc - 1)];
        }

        float rm0 = -1e30f, rm1 = -1e30f;
        #pragma unroll
        for (int nt = 0; nt < 8; nt++) {
            rm0 = fmaxf(rm0, fmaxf(s[nt][0], s[nt][1]));
            rm1 = fmaxf(rm1, fmaxf(s[nt][2], s[nt][3]));
        }
        rm0 = fmaxf(rm0, __shfl_xor_sync(0xffffffffu, rm0, 1));
        rm0 = fmaxf(rm0, __shfl_xor_sync(0xffffffffu, rm0, 2));
        rm1 = fmaxf(rm1, __shfl_xor_sync(0xffffffffu, rm1, 1));
        rm1 = fmaxf(rm1, __shfl_xor_sync(0xffffffffu, rm1, 2));
        float mn0 = fmaxf(m_[0], rm0), mn1 = fmaxf(m_[1], rm1);
        float al0 = __expf(m_[0] - mn0), al1 = __expf(m_[1] - mn1);
        m_[0] = mn0; m_[1] = mn1;
        float sum0 = 0.f, sum1 = 0.f;
        #pragma unroll
        for (int nt = 0; nt < 8; nt++) {
            s[nt][0] = __expf(s[nt][0] - mn0); sum0 += s[nt][0];
            s[nt][1] = __expf(s[nt][1] - mn0); sum0 += s[nt][1];
            s[nt][2] = __expf(s[nt][2] - mn1); sum1 += s[nt][2];
            s[nt][3] = __expf(s[nt][3] - mn1); sum1 += s[nt][3];
        }
        sum0 += __shfl_xor_sync(0xffffffffu, sum0, 1);
        sum0 += __shfl_xor_sync(0xffffffffu, sum0, 2);
        sum1 += __shfl_xor_sync(0xffffffffu, sum1, 1);
        sum1 += __shfl_xor_sync(0xffffffffu, sum1, 2);
        l_[0] = l_[0] * al0 + sum0;
        l_[1] = l_[1] * al1 + sum1;
        #pragma unroll
        for (int nt = 0; nt < 8; nt++) {
            o[nt][0] *= al0; o[nt][1] *= al0;
            o[nt][2] *= al1; o[nt][3] *= al1;
        }

        uint32_t pfh[4][4], pfl[4][4];
        #pragma unroll
        for (int jt = 0; jt < 4; jt++) {
            pfh[jt][0] = pack_hi_h(s[2*jt][0],   s[2*jt][1]);
            pfl[jt][0] = pack_lo_h(s[2*jt][0],   s[2*jt][1]);
            pfh[jt][1] = pack_hi_h(s[2*jt][2],   s[2*jt][3]);
            pfl[jt][1] = pack_lo_h(s[2*jt][2],   s[2*jt][3]);
            pfh[jt][2] = pack_hi_h(s[2*jt+1][0], s[2*jt+1][1]);
            pfl[jt][2] = pack_lo_h(s[2*jt+1][0], s[2*jt+1][1]);
            pfh[jt][3] = pack_hi_h(s[2*jt+1][2], s[2*jt+1][3]);
            pfl[jt][3] = pack_lo_h(s[2*jt+1][2], s[2*jt+1][3]);
        }

        #pragma unroll
        for (int kt = 0; kt < 4; kt++) {
            #pragma unroll
            for (int p = 0; p < 4; p++) {
                uint32_t off = (uint32_t)((p * 16 + (lane & 7) + (lane >> 4) * 8) * ALD
                                          + kt * 16 + ((lane >> 3) & 1) * 8) * 2;
                uint32_t rh[4];
                LDSM4(rh, sb + AVH + off);
                MMA_FP(o[2*p],   pfh[kt], rh);
                MMA_FP(o[2*p],   pfl[kt], rh);
                MMA_FP(o[2*p+1], pfh[kt], rh + 2);
                MMA_FP(o[2*p+1], pfl[kt], rh + 2);
            }
        }
    }

    float inv0 = 1.f / l_[0], inv1 = 1.f / l_[1];
    #pragma unroll
    for (int nt = 0; nt < 8; nt++) {
        int d = nt * 8 + 2 * (lane & 3);
        size_t g00 = hb + (size_t)d * T + i_r;
        size_t g01 = hb + (size_t)(d + 1) * T + i_r;
        Oa[g00]     = __float2half_rn(o[nt][0] * inv0);
        Oa[g01]     = __float2half_rn(o[nt][1] * inv0);
        Oa[g00 + 8] = __float2half_rn(o[nt][2] * inv1);
        Oa[g01 + 8] = __float2half_rn(o[nt][3] * inv1);
    }
}

// ===========================================================================
// Launch
// ===========================================================================
extern "C" void kernel_launch(void* const* d_in, const int* in_sizes, int n_in,
                              void* d_out, int out_size)
{
    const float* x  = (const float*)d_in[0];
    const float* c  = (const float*)d_in[1];
    const float* Wq = (const float*)d_in[3];
    const float* bq = (const float*)d_in[4];
    const float* Wk = (const float*)d_in[5];
    const float* bk = (const float*)d_in[6];
    const float* Wv = (const float*)d_in[7];
    const float* bv = (const float*)d_in[8];
    const float* Wo = (const float*)d_in[9];
    const float* bo = (const float*)d_in[10];
    float* out = (float*)d_out;

    __half *x16, *c16, *qh, *ql, *ks, *vs, *a16;
    __half *wqh, *wql, *wkh, *wkl, *wvh, *wvl, *woh, *wol;
    cudaGetSymbolAddress((void**)&x16, g_x16);
    cudaGetSymbolAddress((void**)&c16, g_c16);
    cudaGetSymbolAddress((void**)&qh, g_q16h); cudaGetSymbolAddress((void**)&ql, g_q16l);
    cudaGetSymbolAddress((void**)&ks, g_k16);  cudaGetSymbolAddress((void**)&vs, g_v16);
    cudaGetSymbolAddress((void**)&a16, g_a16);
    cudaGetSymbolAddress((void**)&wqh, g_wqh); cudaGetSymbolAddress((void**)&wql, g_wql);
    cudaGetSymbolAddress((void**)&wkh, g_wkh); cudaGetSymbolAddress((void**)&wkl, g_wkl);
    cudaGetSymbolAddress((void**)&wvh, g_wvh); cudaGetSymbolAddress((void**)&wvl, g_wvl);
    cudaGetSymbolAddress((void**)&woh, g_woh); cudaGetSymbolAddress((void**)&wol, g_wol);

    cudaFuncSetAttribute(gemm_qkv_kernel,
                         cudaFuncAttributeMaxDynamicSharedMemorySize, GEMM_SMEM);
    cudaFuncSetAttribute(gemm_o_kernel,
                         cudaFuncAttributeMaxDynamicSharedMemorySize, GEMM_SMEM);
    cudaFuncSetAttribute(attn_mma_kernel,
                         cudaFuncAttributeMaxDynamicSharedMemorySize, ATTN_SMEM);

    convert_all_kernel<<<NB_ALL, 256>>>(x, x16, c, c16,
                                        Wq, wqh, wql, Wk, wkh, wkl,
                                        Wv, wvh, wvl, Wo, woh, wol);

    gemm_qkv_kernel<<<dim3(GN / BN, CH / BM, 3 * B_), 256, GEMM_SMEM>>>(
        wqh, wql, bq, wkh, wkl, bk, wvh, wvl, bv,
        x16, c16, qh, ql, ks, vs);

    attn_mma_kernel<<<dim3(T / 64, B_ * H), 128, ATTN_SMEM>>>(
        qh, ql, ks, vs, a16);

    gemm_o_kernel<<<dim3(GN / BN, CH / BM, B_), 256, GEMM_SMEM>>>(
        woh, wol, bo, a16, out);
}

// round 16
// speedup vs baseline: 1.0581x; 1.0528x over previous
#include <cuda_runtime.h>
#include <cuda_bf16.h>
#include <cuda_fp16.h>
#include <cstdint>
#include <math.h>

// Problem constants
constexpr int B_  = 8;
constexpr int CH  = 512;
constexpr int T   = 1024;
constexpr int H   = 8;
constexpr int KC  = 64;    // head dim
constexpr int BAND = 256;  // block_length
constexpr int NEL = B_ * CH * T;        // 4M elements

// ---------------------------------------------------------------------------
// Scratch (__device__ globals; allocation-free rule)
// ---------------------------------------------------------------------------
__device__ __half g_x16[NEL];                    // x single fp16 (B of QKV gemms)
__device__ __half g_c16[NEL];                    // c single fp16
__device__ __half g_q16h[NEL], g_q16l[NEL];      // Q fp16 hi/lo (A of S)
__device__ __half g_k16[NEL];                    // K single fp16
__device__ __half g_v16[NEL];                    // V single fp16
__device__ __half g_a16[NEL];                    // attn out single fp16 (B of O gemm)
__device__ __half g_wqh[CH*CH], g_wql[CH*CH];    // W splits fp16 hi/lo
__device__ __half g_wkh[CH*CH], g_wkl[CH*CH];
__device__ __half g_wvh[CH*CH], g_wvl[CH*CH];
__device__ __half g_woh[CH*CH], g_wol[CH*CH];

// ---------------------------------------------------------------------------
// helpers
// ---------------------------------------------------------------------------
__device__ __forceinline__ uint32_t smem_u32(const void* p) {
    uint32_t a;
    asm("{ .reg .u64 t; cvta.to.shared.u64 t, %1; cvt.u32.u64 %0, t; }"
        : "=r"(a) : "l"(p));
    return a;
}
#define LDSM4(r, addr) \
    asm volatile("ldmatrix.sync.aligned.m8n8.x4.shared.b16 {%0,%1,%2,%3}, [%4];" \
        : "=r"((r)[0]), "=r"((r)[1]), "=r"((r)[2]), "=r"((r)[3]) : "r"(addr))
#define LDSM4T(r, addr) \
    asm volatile("ldmatrix.sync.aligned.m8n8.x4.trans.shared.b16 {%0,%1,%2,%3}, [%4];" \
        : "=r"((r)[0]), "=r"((r)[1]), "=r"((r)[2]), "=r"((r)[3]) : "r"(addr))
#define MMA_FP(d, a, b) \
    asm volatile("mma.sync.aligned.m16n8k16.row.col.f32.f16.f16.f32 " \
        "{%0,%1,%2,%3}, {%4,%5,%6,%7}, {%8,%9}, {%0,%1,%2,%3};" \
        : "+f"((d)[0]), "+f"((d)[1]), "+f"((d)[2]), "+f"((d)[3]) \
        : "r"((a)[0]), "r"((a)[1]), "r"((a)[2]), "r"((a)[3]), \
          "r"((b)[0]), "r"((b)[1]))
#define CP_ASYNC16(saddr, gptr) \
    asm volatile("cp.async.cg.shared.global [%0], [%1], 16;" :: "r"(saddr), "l"(gptr))
#define CP_COMMIT() asm volatile("cp.async.commit_group;" ::: "memory")
#define CP_WAIT0()  asm volatile("cp.async.wait_group 0;" ::: "memory")

__device__ __forceinline__ uint32_t pack_hi_h(float x, float y) {
    __half a = __float2half_rn(x), b = __float2half_rn(y);
    return (uint32_t)__half_as_ushort(a) | ((uint32_t)__half_as_ushort(b) << 16);
}
__device__ __forceinline__ uint32_t pack_lo_h(float x, float y) {
    __half a = __float2half_rn(x), b = __float2half_rn(y);
    __half ra = __float2half_rn(x - __half2float(a));
    __half rb = __float2half_rn(y - __half2float(b));
    return (uint32_t)__half_as_ushort(ra) | ((uint32_t)__half_as_ushort(rb) << 16);
}

// ---------------------------------------------------------------------------
// Fused convert, one launch:
//  x, c -> single fp16;  Wq..Wo -> fp16 hi/lo splits.
// ---------------------------------------------------------------------------
constexpr int NB_BIG = NEL / 4 / 256;       // 4096
constexpr int NB_W   = CH * CH / 4 / 256;   // 256
constexpr int NB_ALL = 2 * NB_BIG + 4 * NB_W;

__global__ void convert_all_kernel(
    const float* __restrict__ x,  __half* __restrict__ x16,
    const float* __restrict__ c,  __half* __restrict__ c16,
    const float* __restrict__ Wq, __half* __restrict__ wqh, __half* __restrict__ wql,
    const float* __restrict__ Wk, __half* __restrict__ wkh, __half* __restrict__ wkl,
    const float* __restrict__ Wv, __half* __restrict__ wvh, __half* __restrict__ wvl,
    const float* __restrict__ Wo, __half* __restrict__ woh, __half* __restrict__ wol)
{
    int bid = blockIdx.x;
    if (bid < 2 * NB_BIG) {
        const float* src = (bid < NB_BIG) ? x : c;
        __half* dst      = (bid < NB_BIG) ? x16 : c16;
        int i = ((bid < NB_BIG) ? bid : bid - NB_BIG) * 256 + threadIdx.x;
        float4 v = ((const float4*)src)[i];
        ((uint2*)dst)[i] = make_uint2(pack_hi_h(v.x, v.y), pack_hi_h(v.z, v.w));
    } else {
        int wb = bid - 2 * NB_BIG;
        int w  = wb / NB_W;
        const float* src; __half *h, *l;
        if (w == 0)      { src = Wq; h = wqh; l = wql; }
        else if (w == 1) { src = Wk; h = wkh; l = wkl; }
        else if (w == 2) { src = Wv; h = wvh; l = wvl; }
        else             { src = Wo; h = woh; l = wol; }
        int i = (wb - w * NB_W) * 256 + threadIdx.x;
        float4 v = ((const float4*)src)[i];
        ((uint2*)h)[i] = make_uint2(pack_hi_h(v.x, v.y), pack_hi_h(v.z, v.w));
        ((uint2*)l)[i] = make_uint2(pack_lo_h(v.x, v.y), pack_lo_h(v.z, v.w));
    }
}

// ===========================================================================
// GEMM core, fp16 2-term: acc = Wh@B + Wl@B (W exact, B single fp16).
// CTA 128x128, K-chunk 64, 8 warps (32x64 warp tile).
// 2-stage cp.async pipeline, ONE __syncthreads per chunk:
//   wait_group(0); sync; issue(c+1); compute(c)
// issue(c+1) writes the stage consumed in compute(c-1); the top-of-loop
// barrier orders that, so no second barrier is needed.
// ===========================================================================
constexpr int GK = 512, GN = 1024;
constexpr int BM = 128, BN = 128, BKC = 64;
constexpr int NCHUNK = GK / BKC;            // 8
constexpr int LDA_S = 72;                   // fp16 elems/row (64 + 8 pad)
constexpr int LDB_S = 136;                  // 128 + 8 pad
constexpr int A_BYTES = BM * LDA_S * 2;     // 18432
constexpr int B_BYTES = BKC * LDB_S * 2;    // 17408
constexpr int OFF_AHI = 0;
constexpr int OFF_ALO = A_BYTES;
constexpr int OFF_B   = 2 * A_BYTES;
constexpr int STAGE   = 2 * A_BYTES + B_BYTES;   // 54272
constexpr int GEMM_SMEM = 2 * STAGE;             // 108544

struct GemmAcc { float a[2][8][4]; };

__device__ __forceinline__ void gemm_mainloop16(
    uint32_t sbase,
    const __half* __restrict__ Ah, const __half* __restrict__ Al,
    const __half* __restrict__ Bb,
    int bm0, int bn0, int tid, int lane, int warp_m, int warp_n, GemmAcc& A)
{
    #pragma unroll
    for (int mt = 0; mt < 2; mt++)
        #pragma unroll
        for (int j = 0; j < 8; j++)
            #pragma unroll
            for (int e = 0; e < 4; e++) A.a[mt][j][e] = 0.f;

    auto issue = [&](int c) {
        const int k0 = c * BKC;
        const uint32_t st = sbase + (c & 1) * STAGE;
        #pragma unroll
        for (int i = 0; i < 4; i++) {
            int idx = tid + i * 256;
            int m = idx >> 3, k16 = idx & 7;            // A: 128 rows x 8 x 16B
            uint32_t ao = st + (uint32_t)(m * LDA_S + k16 * 8) * 2;
            CP_ASYNC16(ao + OFF_AHI, &Ah[(size_t)(bm0 + m) * GK + k0 + k16 * 8]);
            CP_ASYNC16(ao + OFF_ALO, &Al[(size_t)(bm0 + m) * GK + k0 + k16 * 8]);
            int kk = idx >> 4, n8 = idx & 15;           // B: 64 rows x 16 x 16B
            CP_ASYNC16(st + OFF_B + (uint32_t)(kk * LDB_S + n8 * 8) * 2,
                       &Bb[(size_t)(k0 + kk) * GN + bn0 + n8 * 8]);
        }
        CP_COMMIT();
    };

    auto compute = [&](int s) {
        const uint32_t aHi = sbase + s * STAGE + OFF_AHI;
        const uint32_t aLo = sbase + s * STAGE + OFF_ALO;
        const uint32_t bS  = sbase + s * STAGE + OFF_B;
        #pragma unroll
        for (int ks = 0; ks < 4; ks++) {
            const int k0 = ks * 16;
            uint32_t ah[2][4], al[2][4];
            #pragma unroll
            for (int mt = 0; mt < 2; mt++) {
                int m0 = warp_m * 32 + mt * 16;
                uint32_t off = (uint32_t)((m0 + (lane & 15)) * LDA_S
                                          + k0 + (lane >> 4) * 8) * 2;
                LDSM4(ah[mt], aHi + off);
                LDSM4(al[mt], aLo + off);
            }
            uint32_t bh[8][2];
            #pragma unroll
            for (int j2 = 0; j2 < 4; j2++) {
                int n0 = warp_n * 64 + j2 * 16;
                uint32_t off = (uint32_t)((k0 + (lane & 15)) * LDB_S
                                          + n0 + (lane >> 4) * 8) * 2;
                uint32_t r[4];
                LDSM4T(r, bS + off);
                bh[2*j2][0] = r[0]; bh[2*j2][1] = r[1];
                bh[2*j2+1][0] = r[2]; bh[2*j2+1][1] = r[3];
            }
            #pragma unroll
            for (int mt = 0; mt < 2; mt++)
                #pragma unroll
                for (int j = 0; j < 8; j++) {
                    MMA_FP(A.a[mt][j], ah[mt], bh[j]);
                    MMA_FP(A.a[mt][j], al[mt], bh[j]);
                }
        }
    };

    issue(0);
    for (int c = 0; c < NCHUNK; ++c) {
        CP_WAIT0();
        __syncthreads();
        if (c + 1 < NCHUNK) issue(c + 1);
        compute(c & 1);
    }
}

// Fused Q/K/V projection GEMM. z = proj*8 + batch.
__global__ __launch_bounds__(256, 2)
void gemm_qkv_kernel(
    const __half* __restrict__ wqh, const __half* __restrict__ wql, const float* __restrict__ bq,
    const __half* __restrict__ wkh, const __half* __restrict__ wkl, const float* __restrict__ bk,
    const __half* __restrict__ wvh, const __half* __restrict__ wvl, const float* __restrict__ bv,
    const __half* __restrict__ x16, const __half* __restrict__ c16,
    __half* __restrict__ qh, __half* __restrict__ ql,
    __half* __restrict__ ks, __half* __restrict__ vs)
{
    extern __shared__ __align__(128) char smem[];
    const int tid = threadIdx.x, lane = tid & 31, wid = tid >> 5;
    const int warp_m = wid & 3, warp_n = wid >> 2;
    const int proj = blockIdx.z >> 3, b = blockIdx.z & 7;
    const int bm0 = blockIdx.y * BM, bn0 = blockIdx.x * BN;

    const __half *Ah, *Al, *Bg; const float* bias;
    if (proj == 0)      { Ah = wqh; Al = wql; bias = bq; Bg = x16; }
    else if (proj == 1) { Ah = wkh; Al = wkl; bias = bk; Bg = c16; }
    else                { Ah = wvh; Al = wvl; bias = bv; Bg = c16; }
    const __half* Bb = Bg + (size_t)b * GK * GN;

    GemmAcc A;
    gemm_mainloop16(smem_u32(smem), Ah, Al, Bb, bm0, bn0,
                    tid, lane, warp_m, warp_n, A);

    const float scale = (proj == 0) ? 0.125f : 1.0f;
    __half* outs = (proj == 1) ? ks : vs;
    #pragma unroll
    for (int mt = 0; mt < 2; mt++) {
        int m0 = bm0 + warp_m * 32 + mt * 16 + (lane >> 2);
        float bv0 = bias[m0], bv1 = bias[m0 + 8];
        #pragma unroll
        for (int j = 0; j < 8; j++) {
            int n0 = bn0 + warp_n * 64 + j * 8 + 2 * (lane & 3);
            float r00 = (A.a[mt][j][0] + bv0) * scale;
            float r01 = (A.a[mt][j][1] + bv0) * scale;
            float r10 = (A.a[mt][j][2] + bv1) * scale;
            float r11 = (A.a[mt][j][3] + bv1) * scale;
            size_t o0 = (size_t)b * CH * GN + (size_t)m0 * GN + n0;
            size_t o1 = (size_t)b * CH * GN + (size_t)(m0 + 8) * GN + n0;
            if (proj == 0) {
                *(uint32_t*)&qh[o0] = pack_hi_h(r00, r01);
                *(uint32_t*)&ql[o0] = pack_lo_h(r00, r01);
                *(uint32_t*)&qh[o1] = pack_hi_h(r10, r11);
                *(uint32_t*)&ql[o1] = pack_lo_h(r10, r11);
            } else {
                *(uint32_t*)&outs[o0] = pack_hi_h(r00, r01);
                *(uint32_t*)&outs[o1] = pack_hi_h(r10, r11);
            }
        }
    }
}

// O-projection GEMM: fp32 out + bias.
__global__ __launch_bounds__(256, 2)
void gemm_o_kernel(const __half* __restrict__ Ah, const __half* __restrict__ Al,
                   const float* __restrict__ bias,
                   const __half* __restrict__ Bg, float* __restrict__ outf)
{
    extern __shared__ __align__(128) char smem[];
    const int tid = threadIdx.x, lane = tid & 31, wid = tid >> 5;
    const int warp_m = wid & 3, warp_n = wid >> 2;
    const int b = blockIdx.z;
    const int bm0 = blockIdx.y * BM, bn0 = blockIdx.x * BN;
    const __half* Bb = Bg + (size_t)b * GK * GN;

    GemmAcc A;
    gemm_mainloop16(smem_u32(smem), Ah, Al, Bb, bm0, bn0,
                    tid, lane, warp_m, warp_n, A);

    #pragma unroll
    for (int mt = 0; mt < 2; mt++) {
        int m0 = bm0 + warp_m * 32 + mt * 16 + (lane >> 2);
        float bv0 = bias[m0], bv1 = bias[m0 + 8];
        #pragma unroll
        for (int j = 0; j < 8; j++) {
            int n0 = bn0 + warp_n * 64 + j * 8 + 2 * (lane & 3);
            size_t o0 = (size_t)b * CH * GN + (size_t)m0 * GN + n0;
            size_t o1 = (size_t)b * CH * GN + (size_t)(m0 + 8) * GN + n0;
            *(float2*)&outf[o0] = make_float2(A.a[mt][j][0] + bv0, A.a[mt][j][1] + bv0);
            *(float2*)&outf[o1] = make_float2(A.a[mt][j][2] + bv1, A.a[mt][j][3] + bv1);
        }
    }
}

// ===========================================================================
// Banded flash attention, fp16 2-term (unchanged from round 15).
// ===========================================================================
constexpr int ALD = 72;
constexpr int TILE_B = 64 * ALD * 2;
constexpr int AQH = 0, AQL = TILE_B, AKH = 2*TILE_B, AVH = 3*TILE_B, ATAB = 4*TILE_B;
constexpr int ATTN_SMEM = 4 * TILE_B + 512 * 4;   // 38912

__global__ __launch_bounds__(128)
void attn_mma_kernel(const __half* __restrict__ Qh, const __half* __restrict__ Ql,
                     const __half* __restrict__ Kh, const __half* __restrict__ Vh,
                     __half* __restrict__ Oa)
{
    extern __shared__ __align__(128) char sm[];
    float* tab = (float*)(sm + ATAB);
    const uint32_t sb = smem_u32(sm);

    const int bh  = blockIdx.y;
    const int i0  = blockIdx.x * 64;
    const int tid = threadIdx.x;
    const int lane = tid & 31;
    const int warp = tid >> 5;
    const int m0w  = warp * 16;
    const size_t hb = (size_t)bh * KC * T;

    for (int idx = tid; idx < 512; idx += 128)
        tab[idx] = (idx <= BAND) ? -log1pf((float)idx) : -1e30f;

    #pragma unroll
    for (int it = 0; it < 4; it++) {
        int idx = tid + it * 128;
        int d = idx >> 3, c8 = idx & 7;
        *(uint4*)(sm + AQH + (d * ALD + c8 * 8) * 2) =
            *(const uint4*)&Qh[hb + (size_t)d * T + i0 + c8 * 8];
        *(uint4*)(sm + AQL + (d * ALD + c8 * 8) * 2) =
            *(const uint4*)&Ql[hb + (size_t)d * T + i0 + c8 * 8];
    }
    __syncthreads();

    uint32_t qfh[4][4], qfl[4][4];
    #pragma unroll
    for (int kt = 0; kt < 4; kt++) {
        uint32_t roff = (uint32_t)((kt * 16 + (lane & 7) + (lane >> 4) * 8) * ALD
                                   + m0w + ((lane >> 3) & 1) * 8) * 2;
        LDSM4T(qfh[kt], sb + AQH + roff);
        LDSM4T(qfl[kt], sb + AQL + roff);
    }

    float o[8][4];
    #pragma unroll
    for (int nt = 0; nt < 8; nt++)
        #pragma unroll
        for (int e = 0; e < 4; e++) o[nt][e] = 0.f;
    float m_[2] = {-1e30f, -1e30f}, l_[2] = {0.f, 0.f};

    int j_lo = i0 - BAND; if (j_lo < 0) j_lo = 0;
    int j_hi = i0 + BAND; if (j_hi > T - 64) j_hi = T - 64;

    const int i_r = i0 + m0w + (lane >> 2);

    for (int j0 = j_lo; j0 <= j_hi; j0 += 64) {
        __syncthreads();
        #pragma unroll
        for (int it = 0; it < 4; it++) {
            int idx = tid + it * 128;
            int d = idx >> 3, c8 = idx & 7;
            size_t g = hb + (size_t)d * T + j0 + c8 * 8;
            uint32_t so = (uint32_t)(d * ALD + c8 * 8) * 2;
            *(uint4*)(sm + AKH + so) = *(const uint4*)&Kh[g];
            *(uint4*)(sm + AVH + so) = *(const uint4*)&Vh[g];
        }
        __syncthreads();

        float s[8][4];
        #pragma unroll
        for (int nt = 0; nt < 8; nt++)
            #pragma unroll
            for (int e = 0; e < 4; e++) s[nt][e] = 0.f;

        #pragma unroll
        for (int kt = 0; kt < 4; kt++) {
            #pragma unroll
            for (int p = 0; p < 4; p++) {
                uint32_t off = (uint32_t)((kt * 16 + (lane & 15)) * ALD
                                          + p * 16 + (lane >> 4) * 8) * 2;
                uint32_t rh[4];
                LDSM4T(rh, sb + AKH + off);
                MMA_FP(s[2*p],   qfh[kt], rh);
                MMA_FP(s[2*p],   qfl[kt], rh);
                MMA_FP(s[2*p+1], qfh[kt], rh + 2);
                MMA_FP(s[2*p+1], qfl[kt], rh + 2);
            }
        }

        #pragma unroll
        for (int nt = 0; nt < 8; nt++) {
            int jc = j0 + nt * 8 + 2 * (lane & 3);
            s[nt][0] += tab[abs(i_r - jc)];
            s[nt][1] += tab[abs(i_r - jc - 1)];
            s[nt][2] += tab[abs(i_r + 8 - jc)];
            s[nt][3] += tab[abs(i_r + 8 - jc - 1)];
        }

        float rm0 = -1e30f, rm1 = -1e30f;
        #pragma unroll
        for (int nt = 0; nt < 8; nt++) {
            rm0 = fmaxf(rm0, fmaxf(s[nt][0], s[nt][1]));
            rm1 = fmaxf(rm1, fmaxf(s[nt][2], s[nt][3]));
        }
        rm0 = fmaxf(rm0, __shfl_xor_sync(0xffffffffu, rm0, 1));
        rm0 = fmaxf(rm0, __shfl_xor_sync(0xffffffffu, rm0, 2));
        rm1 = fmaxf(rm1, __shfl_xor_sync(0xffffffffu, rm1, 1));
        rm1 = fmaxf(rm1, __shfl_xor_sync(0xffffffffu, rm1, 2));
        float mn0 = fmaxf(m_[0], rm0), mn1 = fmaxf(m_[1], rm1);
        float al0 = __expf(m_[0] - mn0), al1 = __expf(m_[1] - mn1);
        m_[0] = mn0; m_[1] = mn1;
        float sum0 = 0.f, sum1 = 0.f;
        #pragma unroll
        for (int nt = 0; nt < 8; nt++) {
            s[nt][0] = __expf(s[nt][0] - mn0); sum0 += s[nt][0];
            s[nt][1] = __expf(s[nt][1] - mn0); sum0 += s[nt][1];
            s[nt][2] = __expf(s[nt][2] - mn1); sum1 += s[nt][2];
            s[nt][3] = __expf(s[nt][3] - mn1); sum1 += s[nt][3];
        }
        sum0 += __shfl_xor_sync(0xffffffffu, sum0, 1);
        sum0 += __shfl_xor_sync(0xffffffffu, sum0, 2);
        sum1 += __shfl_xor_sync(0xffffffffu, sum1, 1);
        sum1 += __shfl_xor_sync(0xffffffffu, sum1, 2);
        l_[0] = l_[0] * al0 + sum0;
        l_[1] = l_[1] * al1 + sum1;
        #pragma unroll
        for (int nt = 0; nt < 8; nt++) {
            o[nt][0] *= al0; o[nt][1] *= al0;
            o[nt][2] *= al1; o[nt][3] *= al1;
        }

        uint32_t pfh[4][4], pfl[4][4];
        #pragma unroll
        for (int jt = 0; jt < 4; jt++) {
            pfh[jt][0] = pack_hi_h(s[2*jt][0],   s[2*jt][1]);
            pfl[jt][0] = pack_lo_h(s[2*jt][0],   s[2*jt][1]);
            pfh[jt][1] = pack_hi_h(s[2*jt][2],   s[2*jt][3]);
            pfl[jt][1] = pack_lo_h(s[2*jt][2],   s[2*jt][3]);
            pfh[jt][2] = pack_hi_h(s[2*jt+1][0], s[2*jt+1][1]);
            pfl[jt][2] = pack_lo_h(s[2*jt+1][0], s[2*jt+1][1]);
            pfh[jt][3] = pack_hi_h(s[2*jt+1][2], s[2*jt+1][3]);
            pfl[jt][3] = pack_lo_h(s[2*jt+1][2], s[2*jt+1][3]);
        }

        #pragma unroll
        for (int kt = 0; kt < 4; kt++) {
            #pragma unroll
            for (int p = 0; p < 4; p++) {
                uint32_t off = (uint32_t)((p * 16 + (lane & 7) + (lane >> 4) * 8) * ALD
                                          + kt * 16 + ((lane >> 3) & 1) * 8) * 2;
                uint32_t rh[4];
                LDSM4(rh, sb + AVH + off);
                MMA_FP(o[2*p],   pfh[kt], rh);
                MMA_FP(o[2*p],   pfl[kt], rh);
                MMA_FP(o[2*p+1], pfh[kt], rh + 2);
                MMA_FP(o[2*p+1], pfl[kt], rh + 2);
            }
        }
    }

    float inv0 = 1.f / l_[0], inv1 = 1.f / l_[1];
    #pragma unroll
    for (int nt = 0; nt < 8; nt++) {
        int d = nt * 8 + 2 * (lane & 3);
        size_t g00 = hb + (size_t)d * T + i_r;
        size_t g01 = hb + (size_t)(d + 1) * T + i_r;
        Oa[g00]     = __float2half_rn(o[nt][0] * inv0);
        Oa[g01]     = __float2half_rn(o[nt][1] * inv0);
        Oa[g00 + 8] = __float2half_rn(o[nt][2] * inv1);
        Oa[g01 + 8] = __float2half_rn(o[nt][3] * inv1);
    }
}

// ===========================================================================
// Launch
// ===========================================================================
extern "C" void kernel_launch(void* const* d_in, const int* in_sizes, int n_in,
                              void* d_out, int out_size)
{
    const float* x  = (const float*)d_in[0];
    const float* c  = (const float*)d_in[1];
    const float* Wq = (const float*)d_in[3];
    const float* bq = (const float*)d_in[4];
    const float* Wk = (const float*)d_in[5];
    const float* bk = (const float*)d_in[6];
    const float* Wv = (const float*)d_in[7];
    const float* bv = (const float*)d_in[8];
    const float* Wo = (const float*)d_in[9];
    const float* bo = (const float*)d_in[10];
    float* out = (float*)d_out;

    __half *x16, *c16, *qh, *ql, *ks, *vs, *a16;
    __half *wqh, *wql, *wkh, *wkl, *wvh, *wvl, *woh, *wol;
    cudaGetSymbolAddress((void**)&x16, g_x16);
    cudaGetSymbolAddress((void**)&c16, g_c16);
    cudaGetSymbolAddress((void**)&qh, g_q16h); cudaGetSymbolAddress((void**)&ql, g_q16l);
    cudaGetSymbolAddress((void**)&ks, g_k16);  cudaGetSymbolAddress((void**)&vs, g_v16);
    cudaGetSymbolAddress((void**)&a16, g_a16);
    cudaGetSymbolAddress((void**)&wqh, g_wqh); cudaGetSymbolAddress((void**)&wql, g_wql);
    cudaGetSymbolAddress((void**)&wkh, g_wkh); cudaGetSymbolAddress((void**)&wkl, g_wkl);
    cudaGetSymbolAddress((void**)&wvh, g_wvh); cudaGetSymbolAddress((void**)&wvl, g_wvl);
    cudaGetSymbolAddress((void**)&woh, g_woh); cudaGetSymbolAddress((void**)&wol, g_wol);

    cudaFuncSetAttribute(gemm_qkv_kernel,
                         cudaFuncAttributeMaxDynamicSharedMemorySize, GEMM_SMEM);
    cudaFuncSetAttribute(gemm_o_kernel,
                         cudaFuncAttributeMaxDynamicSharedMemorySize, GEMM_SMEM);
    cudaFuncSetAttribute(attn_mma_kernel,
                         cudaFuncAttributeMaxDynamicSharedMemorySize, ATTN_SMEM);

    convert_all_kernel<<<NB_ALL, 256>>>(x, x16, c, c16,
                                        Wq, wqh, wql, Wk, wkh, wkl,
                                        Wv, wvh, wvl, Wo, woh, wol);

    gemm_qkv_kernel<<<dim3(GN / BN, CH / BM, 3 * B_), 256, GEMM_SMEM>>>(
        wqh, wql, bq, wkh, wkl, bk, wvh, wvl, bv,
        x16, c16, qh, ql, ks, vs);

    attn_mma_kernel<<<dim3(T / 64, B_ * H), 128, ATTN_SMEM>>>(
        qh, ql, ks, vs, a16);

    gemm_o_kernel<<<dim3(GN / BN, CH / BM, B_), 256, GEMM_SMEM>>>(
        woh, wol, bo, a16, out);
}

// round 17
// speedup vs baseline: 1.1978x; 1.1321x over previous
#include <cuda_runtime.h>
#include <cuda_bf16.h>
#include <cuda_fp16.h>
#include <cstdint>
#include <math.h>

// Problem constants
constexpr int B_  = 8;
constexpr int CH  = 512;
constexpr int T   = 1024;
constexpr int H   = 8;
constexpr int KC  = 64;    // head dim
constexpr int BAND = 256;  // block_length
constexpr int NEL = B_ * CH * T;        // 4M elements

// ---------------------------------------------------------------------------
// Scratch (__device__ globals; allocation-free rule)
// ---------------------------------------------------------------------------
__device__ __half g_x16[NEL];                    // x single fp16 (B of QKV gemms)
__device__ __half g_c16[NEL];                    // c single fp16
__device__ __half g_q16h[NEL], g_q16l[NEL];      // Q fp16 hi/lo (A of S)
__device__ __half g_k16[NEL];                    // K single fp16
__device__ __half g_v16[NEL];                    // V single fp16
__device__ __half g_a16[NEL];                    // attn out single fp16 (B of O gemm)
__device__ __half g_wqh[CH*CH], g_wql[CH*CH];    // W splits fp16 hi/lo
__device__ __half g_wkh[CH*CH], g_wkl[CH*CH];
__device__ __half g_wvh[CH*CH], g_wvl[CH*CH];
__device__ __half g_woh[CH*CH], g_wol[CH*CH];

// ---------------------------------------------------------------------------
// helpers
// ---------------------------------------------------------------------------
__device__ __forceinline__ uint32_t smem_u32(const void* p) {
    uint32_t a;
    asm("{ .reg .u64 t; cvta.to.shared.u64 t, %1; cvt.u32.u64 %0, t; }"
        : "=r"(a) : "l"(p));
    return a;
}
#define LDSM4(r, addr) \
    asm volatile("ldmatrix.sync.aligned.m8n8.x4.shared.b16 {%0,%1,%2,%3}, [%4];" \
        : "=r"((r)[0]), "=r"((r)[1]), "=r"((r)[2]), "=r"((r)[3]) : "r"(addr))
#define LDSM4T(r, addr) \
    asm volatile("ldmatrix.sync.aligned.m8n8.x4.trans.shared.b16 {%0,%1,%2,%3}, [%4];" \
        : "=r"((r)[0]), "=r"((r)[1]), "=r"((r)[2]), "=r"((r)[3]) : "r"(addr))
#define MMA_FP(d, a, b) \
    asm volatile("mma.sync.aligned.m16n8k16.row.col.f32.f16.f16.f32 " \
        "{%0,%1,%2,%3}, {%4,%5,%6,%7}, {%8,%9}, {%0,%1,%2,%3};" \
        : "+f"((d)[0]), "+f"((d)[1]), "+f"((d)[2]), "+f"((d)[3]) \
        : "r"((a)[0]), "r"((a)[1]), "r"((a)[2]), "r"((a)[3]), \
          "r"((b)[0]), "r"((b)[1]))
#define CP_ASYNC16(saddr, gptr) \
    asm volatile("cp.async.cg.shared.global [%0], [%1], 16;" :: "r"(saddr), "l"(gptr))
#define CP_COMMIT() asm volatile("cp.async.commit_group;" ::: "memory")
#define CP_WAIT0()  asm volatile("cp.async.wait_group 0;" ::: "memory")

__device__ __forceinline__ uint32_t pack_hi_h(float x, float y) {
    __half a = __float2half_rn(x), b = __float2half_rn(y);
    return (uint32_t)__half_as_ushort(a) | ((uint32_t)__half_as_ushort(b) << 16);
}
__device__ __forceinline__ uint32_t pack_lo_h(float x, float y) {
    __half a = __float2half_rn(x), b = __float2half_rn(y);
    __half ra = __float2half_rn(x - __half2float(a));
    __half rb = __float2half_rn(y - __half2float(b));
    return (uint32_t)__half_as_ushort(ra) | ((uint32_t)__half_as_ushort(rb) << 16);
}

// ---------------------------------------------------------------------------
// Fused convert, one launch:
//  x, c -> single fp16;  Wq..Wo -> fp16 hi/lo splits.
// ---------------------------------------------------------------------------
constexpr int NB_BIG = NEL / 4 / 256;       // 4096
constexpr int NB_W   = CH * CH / 4 / 256;   // 256
constexpr int NB_ALL = 2 * NB_BIG + 4 * NB_W;

__global__ void convert_all_kernel(
    const float* __restrict__ x,  __half* __restrict__ x16,
    const float* __restrict__ c,  __half* __restrict__ c16,
    const float* __restrict__ Wq, __half* __restrict__ wqh, __half* __restrict__ wql,
    const float* __restrict__ Wk, __half* __restrict__ wkh, __half* __restrict__ wkl,
    const float* __restrict__ Wv, __half* __restrict__ wvh, __half* __restrict__ wvl,
    const float* __restrict__ Wo, __half* __restrict__ woh, __half* __restrict__ wol)
{
    int bid = blockIdx.x;
    if (bid < 2 * NB_BIG) {
        const float* src = (bid < NB_BIG) ? x : c;
        __half* dst      = (bid < NB_BIG) ? x16 : c16;
        int i = ((bid < NB_BIG) ? bid : bid - NB_BIG) * 256 + threadIdx.x;
        float4 v = ((const float4*)src)[i];
        ((uint2*)dst)[i] = make_uint2(pack_hi_h(v.x, v.y), pack_hi_h(v.z, v.w));
    } else {
        int wb = bid - 2 * NB_BIG;
        int w  = wb / NB_W;
        const float* src; __half *h, *l;
        if (w == 0)      { src = Wq; h = wqh; l = wql; }
        else if (w == 1) { src = Wk; h = wkh; l = wkl; }
        else if (w == 2) { src = Wv; h = wvh; l = wvl; }
        else             { src = Wo; h = woh; l = wol; }
        int i = (wb - w * NB_W) * 256 + threadIdx.x;
        float4 v = ((const float4*)src)[i];
        ((uint2*)h)[i] = make_uint2(pack_hi_h(v.x, v.y), pack_hi_h(v.z, v.w));
        ((uint2*)l)[i] = make_uint2(pack_lo_h(v.x, v.y), pack_lo_h(v.z, v.w));
    }
}

// ===========================================================================
// GEMM core, templated on term count:
//   TWO_TERM: acc = Wh@B + Wl@B   (W exact;  Q and O projections)
//   !TWO_TERM: acc = Wh@B         (K and V projections — their outputs are
//              rounded to single fp16 anyway, so the Wl term is wasted work)
// CTA 128x128, K-chunk 64, 8 warps. 2-stage cp.async, one barrier per chunk.
// ===========================================================================
constexpr int GK = 512, GN = 1024;
constexpr int BM = 128, BN = 128, BKC = 64;
constexpr int NCHUNK = GK / BKC;            // 8
constexpr int LDA_S = 72;                   // fp16 elems/row (64 + 8 pad)
constexpr int LDB_S = 136;                  // 128 + 8 pad
constexpr int A_BYTES = BM * LDA_S * 2;     // 18432
constexpr int B_BYTES = BKC * LDB_S * 2;    // 17408
constexpr int OFF_AHI = 0;
constexpr int OFF_ALO = A_BYTES;
constexpr int OFF_B   = 2 * A_BYTES;
constexpr int STAGE   = 2 * A_BYTES + B_BYTES;   // 54272
constexpr int GEMM_SMEM = 2 * STAGE;             // 108544

struct GemmAcc { float a[2][8][4]; };

template <bool TWO_TERM>
__device__ __forceinline__ void gemm_mainloop16(
    uint32_t sbase,
    const __half* __restrict__ Ah, const __half* __restrict__ Al,
    const __half* __restrict__ Bb,
    int bm0, int bn0, int tid, int lane, int warp_m, int warp_n, GemmAcc& A)
{
    #pragma unroll
    for (int mt = 0; mt < 2; mt++)
        #pragma unroll
        for (int j = 0; j < 8; j++)
            #pragma unroll
            for (int e = 0; e < 4; e++) A.a[mt][j][e] = 0.f;

    auto issue = [&](int c) {
        const int k0 = c * BKC;
        const uint32_t st = sbase + (c & 1) * STAGE;
        #pragma unroll
        for (int i = 0; i < 4; i++) {
            int idx = tid + i * 256;
            int m = idx >> 3, k16 = idx & 7;            // A: 128 rows x 8 x 16B
            uint32_t ao = st + (uint32_t)(m * LDA_S + k16 * 8) * 2;
            CP_ASYNC16(ao + OFF_AHI, &Ah[(size_t)(bm0 + m) * GK + k0 + k16 * 8]);
            if (TWO_TERM)
                CP_ASYNC16(ao + OFF_ALO, &Al[(size_t)(bm0 + m) * GK + k0 + k16 * 8]);
            int kk = idx >> 4, n8 = idx & 15;           // B: 64 rows x 16 x 16B
            CP_ASYNC16(st + OFF_B + (uint32_t)(kk * LDB_S + n8 * 8) * 2,
                       &Bb[(size_t)(k0 + kk) * GN + bn0 + n8 * 8]);
        }
        CP_COMMIT();
    };

    auto compute = [&](int s) {
        const uint32_t aHi = sbase + s * STAGE + OFF_AHI;
        const uint32_t aLo = sbase + s * STAGE + OFF_ALO;
        const uint32_t bS  = sbase + s * STAGE + OFF_B;
        #pragma unroll
        for (int ks = 0; ks < 4; ks++) {
            const int k0 = ks * 16;
            uint32_t ah[2][4], al[2][4];
            #pragma unroll
            for (int mt = 0; mt < 2; mt++) {
                int m0 = warp_m * 32 + mt * 16;
                uint32_t off = (uint32_t)((m0 + (lane & 15)) * LDA_S
                                          + k0 + (lane >> 4) * 8) * 2;
                LDSM4(ah[mt], aHi + off);
                if (TWO_TERM) LDSM4(al[mt], aLo + off);
            }
            uint32_t bh[8][2];
            #pragma unroll
            for (int j2 = 0; j2 < 4; j2++) {
                int n0 = warp_n * 64 + j2 * 16;
                uint32_t off = (uint32_t)((k0 + (lane & 15)) * LDB_S
                                          + n0 + (lane >> 4) * 8) * 2;
                uint32_t r[4];
                LDSM4T(r, bS + off);
                bh[2*j2][0] = r[0]; bh[2*j2][1] = r[1];
                bh[2*j2+1][0] = r[2]; bh[2*j2+1][1] = r[3];
            }
            #pragma unroll
            for (int mt = 0; mt < 2; mt++)
                #pragma unroll
                for (int j = 0; j < 8; j++) {
                    MMA_FP(A.a[mt][j], ah[mt], bh[j]);
                    if (TWO_TERM) MMA_FP(A.a[mt][j], al[mt], bh[j]);
                }
        }
    };

    issue(0);
    for (int c = 0; c < NCHUNK; ++c) {
        CP_WAIT0();
        __syncthreads();
        if (c + 1 < NCHUNK) issue(c + 1);
        compute(c & 1);
    }
}

// Fused Q/K/V projection GEMM. z = proj*8 + batch.
// Q: 2-term (its hi/lo output is the exact operand of the S split).
// K, V: 1-term (outputs are rounded to single fp16 downstream anyway).
__global__ __launch_bounds__(256, 2)
void gemm_qkv_kernel(
    const __half* __restrict__ wqh, const __half* __restrict__ wql, const float* __restrict__ bq,
    const __half* __restrict__ wkh, const float* __restrict__ bk,
    const __half* __restrict__ wvh, const float* __restrict__ bv,
    const __half* __restrict__ x16, const __half* __restrict__ c16,
    __half* __restrict__ qh, __half* __restrict__ ql,
    __half* __restrict__ ks, __half* __restrict__ vs)
{
    extern __shared__ __align__(128) char smem[];
    const int tid = threadIdx.x, lane = tid & 31, wid = tid >> 5;
    const int warp_m = wid & 3, warp_n = wid >> 2;
    const int proj = blockIdx.z >> 3, b = blockIdx.z & 7;
    const int bm0 = blockIdx.y * BM, bn0 = blockIdx.x * BN;

    GemmAcc A;
    const float* bias;
    if (proj == 0) {
        bias = bq;
        gemm_mainloop16<true>(smem_u32(smem), wqh, wql,
                              x16 + (size_t)b * GK * GN,
                              bm0, bn0, tid, lane, warp_m, warp_n, A);
    } else {
        const __half* Ah = (proj == 1) ? wkh : wvh;
        bias             = (proj == 1) ? bk  : bv;
        gemm_mainloop16<false>(smem_u32(smem), Ah, nullptr,
                               c16 + (size_t)b * GK * GN,
                               bm0, bn0, tid, lane, warp_m, warp_n, A);
    }

    const float scale = (proj == 0) ? 0.125f : 1.0f;
    __half* outs = (proj == 1) ? ks : vs;
    #pragma unroll
    for (int mt = 0; mt < 2; mt++) {
        int m0 = bm0 + warp_m * 32 + mt * 16 + (lane >> 2);
        float bv0 = bias[m0], bv1 = bias[m0 + 8];
        #pragma unroll
        for (int j = 0; j < 8; j++) {
            int n0 = bn0 + warp_n * 64 + j * 8 + 2 * (lane & 3);
            float r00 = (A.a[mt][j][0] + bv0) * scale;
            float r01 = (A.a[mt][j][1] + bv0) * scale;
            float r10 = (A.a[mt][j][2] + bv1) * scale;
            float r11 = (A.a[mt][j][3] + bv1) * scale;
            size_t o0 = (size_t)b * CH * GN + (size_t)m0 * GN + n0;
            size_t o1 = (size_t)b * CH * GN + (size_t)(m0 + 8) * GN + n0;
            if (proj == 0) {
                *(uint32_t*)&qh[o0] = pack_hi_h(r00, r01);
                *(uint32_t*)&ql[o0] = pack_lo_h(r00, r01);
                *(uint32_t*)&qh[o1] = pack_hi_h(r10, r11);
                *(uint32_t*)&ql[o1] = pack_lo_h(r10, r11);
            } else {
                *(uint32_t*)&outs[o0] = pack_hi_h(r00, r01);
                *(uint32_t*)&outs[o1] = pack_hi_h(r10, r11);
            }
        }
    }
}

// O-projection GEMM: 2-term, fp32 out + bias.
__global__ __launch_bounds__(256, 2)
void gemm_o_kernel(const __half* __restrict__ Ah, const __half* __restrict__ Al,
                   const float* __restrict__ bias,
                   const __half* __restrict__ Bg, float* __restrict__ outf)
{
    extern __shared__ __align__(128) char smem[];
    const int tid = threadIdx.x, lane = tid & 31, wid = tid >> 5;
    const int warp_m = wid & 3, warp_n = wid >> 2;
    const int b = blockIdx.z;
    const int bm0 = blockIdx.y * BM, bn0 = blockIdx.x * BN;

    GemmAcc A;
    gemm_mainloop16<true>(smem_u32(smem), Ah, Al, Bg + (size_t)b * GK * GN,
                          bm0, bn0, tid, lane, warp_m, warp_n, A);

    #pragma unroll
    for (int mt = 0; mt < 2; mt++) {
        int m0 = bm0 + warp_m * 32 + mt * 16 + (lane >> 2);
        float bv0 = bias[m0], bv1 = bias[m0 + 8];
        #pragma unroll
        for (int j = 0; j < 8; j++) {
            int n0 = bn0 + warp_n * 64 + j * 8 + 2 * (lane & 3);
            size_t o0 = (size_t)b * CH * GN + (size_t)m0 * GN + n0;
            size_t o1 = (size_t)b * CH * GN + (size_t)(m0 + 8) * GN + n0;
            *(float2*)&outf[o0] = make_float2(A.a[mt][j][0] + bv0, A.a[mt][j][1] + bv0);
            *(float2*)&outf[o1] = make_float2(A.a[mt][j][2] + bv1, A.a[mt][j][3] + bv1);
        }
    }
}

// ===========================================================================
// Banded flash attention, fp16 2-term (unchanged).
// ===========================================================================
constexpr int ALD = 72;
constexpr int TILE_B = 64 * ALD * 2;
constexpr int AQH = 0, AQL = TILE_B, AKH = 2*TILE_B, AVH = 3*TILE_B, ATAB = 4*TILE_B;
constexpr int ATTN_SMEM = 4 * TILE_B + 512 * 4;   // 38912

__global__ __launch_bounds__(128)
void attn_mma_kernel(const __half* __restrict__ Qh, const __half* __restrict__ Ql,
                     const __half* __restrict__ Kh, const __half* __restrict__ Vh,
                     __half* __restrict__ Oa)
{
    extern __shared__ __align__(128) char sm[];
    float* tab = (float*)(sm + ATAB);
    const uint32_t sb = smem_u32(sm);

    const int bh  = blockIdx.y;
    const int i0  = blockIdx.x * 64;
    const int tid = threadIdx.x;
    const int lane = tid & 31;
    const int warp = tid >> 5;
    const int m0w  = warp * 16;
    const size_t hb = (size_t)bh * KC * T;

    for (int idx = tid; idx < 512; idx += 128)
        tab[idx] = (idx <= BAND) ? -log1pf((float)idx) : -1e30f;

    #pragma unroll
    for (int it = 0; it < 4; it++) {
        int idx = tid + it * 128;
        int d = idx >> 3, c8 = idx & 7;
        *(uint4*)(sm + AQH + (d * ALD + c8 * 8) * 2) =
            *(const uint4*)&Qh[hb + (size_t)d * T + i0 + c8 * 8];
        *(uint4*)(sm + AQL + (d * ALD + c8 * 8) * 2) =
            *(const uint4*)&Ql[hb + (size_t)d * T + i0 + c8 * 8];
    }
    __syncthreads();

    uint32_t qfh[4][4], qfl[4][4];
    #pragma unroll
    for (int kt = 0; kt < 4; kt++) {
        uint32_t roff = (uint32_t)((kt * 16 + (lane & 7) + (lane >> 4) * 8) * ALD
                                   + m0w + ((lane >> 3) & 1) * 8) * 2;
        LDSM4T(qfh[kt], sb + AQH + roff);
        LDSM4T(qfl[kt], sb + AQL + roff);
    }

    float o[8][4];
    #pragma unroll
    for (int nt = 0; nt < 8; nt++)
        #pragma unroll
        for (int e = 0; e < 4; e++) o[nt][e] = 0.f;
    float m_[2] = {-1e30f, -1e30f}, l_[2] = {0.f, 0.f};

    int j_lo = i0 - BAND; if (j_lo < 0) j_lo = 0;
    int j_hi = i0 + BAND; if (j_hi > T - 64) j_hi = T - 64;

    const int i_r = i0 + m0w + (lane >> 2);

    for (int j0 = j_lo; j0 <= j_hi; j0 += 64) {
        __syncthreads();
        #pragma unroll
        for (int it = 0; it < 4; it++) {
            int idx = tid + it * 128;
            int d = idx >> 3, c8 = idx & 7;
            size_t g = hb + (size_t)d * T + j0 + c8 * 8;
            uint32_t so = (uint32_t)(d * ALD + c8 * 8) * 2;
            *(uint4*)(sm + AKH + so) = *(const uint4*)&Kh[g];
            *(uint4*)(sm + AVH + so) = *(const uint4*)&Vh[g];
        }
        __syncthreads();

        float s[8][4];
        #pragma unroll
        for (int nt = 0; nt < 8; nt++)
            #pragma unroll
            for (int e = 0; e < 4; e++) s[nt][e] = 0.f;

        #pragma unroll
        for (int kt = 0; kt < 4; kt++) {
            #pragma unroll
            for (int p = 0; p < 4; p++) {
                uint32_t off = (uint32_t)((kt * 16 + (lane & 15)) * ALD
                                          + p * 16 + (lane >> 4) * 8) * 2;
                uint32_t rh[4];
                LDSM4T(rh, sb + AKH + off);
                MMA_FP(s[2*p],   qfh[kt], rh);
                MMA_FP(s[2*p],   qfl[kt], rh);
                MMA_FP(s[2*p+1], qfh[kt], rh + 2);
                MMA_FP(s[2*p+1], qfl[kt], rh + 2);
            }
        }

        #pragma unroll
        for (int nt = 0; nt < 8; nt++) {
            int jc = j0 + nt * 8 + 2 * (lane & 3);
            s[nt][0] += tab[abs(i_r - jc)];
            s[nt][1] += tab[abs(i_r - jc - 1)];
            s[nt][2] += tab[abs(i_r + 8 - jc)];
            s[nt][3] += tab[abs(i_r + 8 - jc - 1)];
        }

        float rm0 = -1e30f, rm1 = -1e30f;
        #pragma unroll
        for (int nt = 0; nt < 8; nt++) {
            rm0 = fmaxf(rm0, fmaxf(s[nt][0], s[nt][1]));
            rm1 = fmaxf(rm1, fmaxf(s[nt][2], s[nt][3]));
        }
        rm0 = fmaxf(rm0, __shfl_xor_sync(0xffffffffu, rm0, 1));
        rm0 = fmaxf(rm0, __shfl_xor_sync(0xffffffffu, rm0, 2));
        rm1 = fmaxf(rm1, __shfl_xor_sync(0xffffffffu, rm1, 1));
        rm1 = fmaxf(rm1, __shfl_xor_sync(0xffffffffu, rm1, 2));
        float mn0 = fmaxf(m_[0], rm0), mn1 = fmaxf(m_[1], rm1);
        float al0 = __expf(m_[0] - mn0), al1 = __expf(m_[1] - mn1);
        m_[0] = mn0; m_[1] = mn1;
        float sum0 = 0.f, sum1 = 0.f;
        #pragma unroll
        for (int nt = 0; nt < 8; nt++) {
            s[nt][0] = __expf(s[nt][0] - mn0); sum0 += s[nt][0];
            s[nt][1] = __expf(s[nt][1] - mn0); sum0 += s[nt][1];
            s[nt][2] = __expf(s[nt][2] - mn1); sum1 += s[nt][2];
            s[nt][3] = __expf(s[nt][3] - mn1); sum1 += s[nt][3];
        }
        sum0 += __shfl_xor_sync(0xffffffffu, sum0, 1);
        sum0 += __shfl_xor_sync(0xffffffffu, sum0, 2);
        sum1 += __shfl_xor_sync(0xffffffffu, sum1, 1);
        sum1 += __shfl_xor_sync(0xffffffffu, sum1, 2);
        l_[0] = l_[0] * al0 + sum0;
        l_[1] = l_[1] * al1 + sum1;
        #pragma unroll
        for (int nt = 0; nt < 8; nt++) {
            o[nt][0] *= al0; o[nt][1] *= al0;
            o[nt][2] *= al1; o[nt][3] *= al1;
        }

        uint32_t pfh[4][4], pfl[4][4];
        #pragma unroll
        for (int jt = 0; jt < 4; jt++) {
            pfh[jt][0] = pack_hi_h(s[2*jt][0],   s[2*jt][1]);
            pfl[jt][0] = pack_lo_h(s[2*jt][0],   s[2*jt][1]);
            pfh[jt][1] = pack_hi_h(s[2*jt][2],   s[2*jt][3]);
            pfl[jt][1] = pack_lo_h(s[2*jt][2],   s[2*jt][3]);
            pfh[jt][2] = pack_hi_h(s[2*jt+1][0], s[2*jt+1][1]);
            pfl[jt][2] = pack_lo_h(s[2*jt+1][0], s[2*jt+1][1]);
            pfh[jt][3] = pack_hi_h(s[2*jt+1][2], s[2*jt+1][3]);
            pfl[jt][3] = pack_lo_h(s[2*jt+1][2], s[2*jt+1][3]);
        }

        #pragma unroll
        for (int kt = 0; kt < 4; kt++) {
            #pragma unroll
            for (int p = 0; p < 4; p++) {
                uint32_t off = (uint32_t)((p * 16 + (lane & 7) + (lane >> 4) * 8) * ALD
                                          + kt * 16 + ((lane >> 3) & 1) * 8) * 2;
                uint32_t rh[4];
                LDSM4(rh, sb + AVH + off);
                MMA_FP(o[2*p],   pfh[kt], rh);
                MMA_FP(o[2*p],   pfl[kt], rh);
                MMA_FP(o[2*p+1], pfh[kt], rh + 2);
                MMA_FP(o[2*p+1], pfl[kt], rh + 2);
            }
        }
    }

    float inv0 = 1.f / l_[0], inv1 = 1.f / l_[1];
    #pragma unroll
    for (int nt = 0; nt < 8; nt++) {
        int d = nt * 8 + 2 * (lane & 3);
        size_t g00 = hb + (size_t)d * T + i_r;
        size_t g01 = hb + (size_t)(d + 1) * T + i_r;
        Oa[g00]     = __float2half_rn(o[nt][0] * inv0);
        Oa[g01]     = __float2half_rn(o[nt][1] * inv0);
        Oa[g00 + 8] = __float2half_rn(o[nt][2] * inv1);
        Oa[g01 + 8] = __float2half_rn(o[nt][3] * inv1);
    }
}

// ===========================================================================
// Launch
// ===========================================================================
extern "C" void kernel_launch(void* const* d_in, const int* in_sizes, int n_in,
                              void* d_out, int out_size)
{
    const float* x  = (const float*)d_in[0];
    const float* c  = (const float*)d_in[1];
    const float* Wq = (const float*)d_in[3];
    const float* bq = (const float*)d_in[4];
    const float* Wk = (const float*)d_in[5];
    const float* bk = (const float*)d_in[6];
    const float* Wv = (const float*)d_in[7];
    const float* bv = (const float*)d_in[8];
    const float* Wo = (const float*)d_in[9];
    const float* bo = (const float*)d_in[10];
    float* out = (float*)d_out;

    __half *x16, *c16, *qh, *ql, *ks, *vs, *a16;
    __half *wqh, *wql, *wkh, *wkl, *wvh, *wvl, *woh, *wol;
    cudaGetSymbolAddress((void**)&x16, g_x16);
    cudaGetSymbolAddress((void**)&c16, g_c16);
    cudaGetSymbolAddress((void**)&qh, g_q16h); cudaGetSymbolAddress((void**)&ql, g_q16l);
    cudaGetSymbolAddress((void**)&ks, g_k16);  cudaGetSymbolAddress((void**)&vs, g_v16);
    cudaGetSymbolAddress((void**)&a16, g_a16);
    cudaGetSymbolAddress((void**)&wqh, g_wqh); cudaGetSymbolAddress((void**)&wql, g_wql);
    cudaGetSymbolAddress((void**)&wkh, g_wkh); cudaGetSymbolAddress((void**)&wkl, g_wkl);
    cudaGetSymbolAddress((void**)&wvh, g_wvh); cudaGetSymbolAddress((void**)&wvl, g_wvl);
    cudaGetSymbolAddress((void**)&woh, g_woh); cudaGetSymbolAddress((void**)&wol, g_wol);

    cudaFuncSetAttribute(gemm_qkv_kernel,
                         cudaFuncAttributeMaxDynamicSharedMemorySize, GEMM_SMEM);
    cudaFuncSetAttribute(gemm_o_kernel,
                         cudaFuncAttributeMaxDynamicSharedMemorySize, GEMM_SMEM);
    cudaFuncSetAttribute(attn_mma_kernel,
                         cudaFuncAttributeMaxDynamicSharedMemorySize, ATTN_SMEM);

    convert_all_kernel<<<NB_ALL, 256>>>(x, x16, c, c16,
                                        Wq, wqh, wql, Wk, wkh, wkl,
                                        Wv, wvh, wvl, Wo, woh, wol);

    gemm_qkv_kernel<<<dim3(GN / BN, CH / BM, 3 * B_), 256, GEMM_SMEM>>>(
        wqh, wql, bq, wkh, bk, wvh, bv,
        x16, c16, qh, ql, ks, vs);

    attn_mma_kernel<<<dim3(T / 64, B_ * H), 128, ATTN_SMEM>>>(
        qh, ql, ks, vs, a16);

    gemm_o_kernel<<<dim3(GN / BN, CH / BM, B_), 256, GEMM_SMEM>>>(
        woh, wol, bo, a16, out);
}